// round 10
// baseline (speedup 1.0000x reference)
#include <cuda_runtime.h>
#include <cuda_fp16.h>
#include <cstdint>

// ---------------------------------------------------------------------------
// Problem constants
// ---------------------------------------------------------------------------
#define T_TOK   2048
#define D_DIM   2880
#define S_LEN   1024
#define B_BATCH 2
#define WIN     128
#define NH      4096
#define KVH     512
#define QKV_COLS 5120
#define OPAD    2944
#define NKC_QKV 90        // 2880/32
#define NKC_O   128       // 4096/32

// ---------------------------------------------------------------------------
// Scratch
// ---------------------------------------------------------------------------
__device__ __half g_xpk [(size_t)16 * NKC_QKV * 128 * 32];   // x packed fp16 (A blobs)
__device__ __half g_wbh [(size_t)40 * NKC_QKV * 128 * 32];   // qkv weights (B blobs)
__device__ __half g_wobh[(size_t)23 * NKC_O   * 128 * 32];   // wo (B blobs)
__device__ __half g_cpk [(size_t)16 * NKC_O   * 128 * 32];   // ctx packed fp16 (A blobs)
__device__ float  g_qkv  [(size_t)T_TOK * QKV_COLS];
__device__ float  g_qkvp [(size_t)T_TOK * QKV_COLS];         // QKV pre-rope plane
__device__ float  g_opart[(size_t)2 * T_TOK * OPAD];         // O split-K partials
__device__ float  g_biasqkv[QKV_COLS];

// ---------------------------------------------------------------------------
// Packed layout: 128-row x 32-k tiles, row = 64B, 16B chunks XOR-swizzled by
// ((row>>1)&3) so ldmatrix is conflict-free while bulk copies stay linear.
// ---------------------------------------------------------------------------
__device__ __forceinline__ size_t offP(int r_glob, int k, int nkc) {
    int r = r_glob & 127, ck = (k >> 3) & 3, w = k & 7;
    return ((((size_t)(r_glob >> 7)) * nkc + (k >> 5)) * 128 + r) * 32 +
           (((ck ^ ((r >> 1) & 3)) << 3) + w);
}

// ---------------------------------------------------------------------------
// PTX helpers
// ---------------------------------------------------------------------------
__device__ __forceinline__ void mbar_init(uint32_t a, uint32_t cnt) {
    asm volatile("mbarrier.init.shared.b64 [%0], %1;" :: "r"(a), "r"(cnt) : "memory");
}
__device__ __forceinline__ void mbar_wait(uint32_t a, int ph) {
    uint32_t done = 0;
    while (!done) {
        asm volatile("{\n\t.reg .pred p;\n\t"
                     "mbarrier.try_wait.parity.acquire.cta.shared::cta.b64 p, [%1], %2, 0x989680;\n\t"
                     "selp.b32 %0,1,0,p;\n\t}"
                     : "=r"(done) : "r"(a), "r"((uint32_t)ph) : "memory");
    }
}
__device__ __forceinline__ void expect_tx(uint32_t a, uint32_t bytes) {
    asm volatile("mbarrier.arrive.expect_tx.shared::cta.b64 _, [%0], %1;"
                 :: "r"(a), "r"(bytes) : "memory");
}
__device__ __forceinline__ void bulk_g2s(uint32_t sdst, const void* gsrc,
                                         uint32_t bytes, uint32_t mbar) {
    asm volatile("cp.async.bulk.shared::cluster.global.mbarrier::complete_tx::bytes "
                 "[%0], [%1], %2, [%3];"
                 :: "r"(sdst), "l"(__cvta_generic_to_global(gsrc)), "r"(bytes), "r"(mbar)
                 : "memory");
}
__device__ __forceinline__ void ldmx4(uint32_t* d, uint32_t addr) {
    asm volatile("ldmatrix.sync.aligned.m8n8.x4.shared.b16 {%0,%1,%2,%3}, [%4];"
                 : "=r"(d[0]), "=r"(d[1]), "=r"(d[2]), "=r"(d[3]) : "r"(addr));
}
__device__ __forceinline__ void mma16816(float* c, const uint32_t* a, const uint32_t* b) {
    asm volatile(
        "mma.sync.aligned.m16n8k16.row.col.f32.f16.f16.f32 "
        "{%0,%1,%2,%3},{%4,%5,%6,%7},{%8,%9},{%0,%1,%2,%3};\n"
        : "+f"(c[0]), "+f"(c[1]), "+f"(c[2]), "+f"(c[3])
        : "r"(a[0]), "r"(a[1]), "r"(a[2]), "r"(a[3]), "r"(b[0]), "r"(b[1]));
}

// fast exp on the FMA pipe (x <= 0 path), rel err ~1e-7
__device__ __forceinline__ float fexp(float x) {
    x = fmaxf(x, -87.0f);
    float y = x * 1.44269504f;
    float n = rintf(y);
    float f = y - n;
    float p = 1.33336498e-3f;
    p = fmaf(p, f, 9.61011233e-3f);
    p = fmaf(p, f, 5.55040755e-2f);
    p = fmaf(p, f, 2.40226507e-1f);
    p = fmaf(p, f, 6.93147182e-1f);
    p = fmaf(p, f, 1.0f);
    return p * __int_as_float(((int)n + 127) << 23);
}

// ---------------------------------------------------------------------------
// Prep kernels
// ---------------------------------------------------------------------------
__global__ void pack_x(const float* __restrict__ x, __half* __restrict__ o) {
    int k = blockIdx.x * 256 + threadIdx.x;
    int t = blockIdx.y;
    if (k < D_DIM)
        o[offP(t, k, NKC_QKV)] = __float2half_rn(x[(size_t)t * D_DIM + k]);
}

// transpose single-plane into packed B layout
__global__ void tsp1(const float* __restrict__ in, __half* __restrict__ oh,
                     int R, int C, int nkc, int nbase) {
    __shared__ float tb[32][33];
    int c0 = blockIdx.x * 32, r0 = blockIdx.y * 32;
    int tx = threadIdx.x, ty = threadIdx.y;
#pragma unroll
    for (int i = 0; i < 4; i++) {
        int r = r0 + ty + i * 8, c = c0 + tx;
        tb[ty + i * 8][tx] = (c < C) ? in[(size_t)r * C + c] : 0.0f;
    }
    __syncthreads();
#pragma unroll
    for (int i = 0; i < 4; i++) {
        int n = nbase + c0 + ty + i * 8, k = r0 + tx;
        oh[offP(n, k, nkc)] = __float2half_rn(tb[tx][ty + i * 8]);
    }
}

__global__ void concat_bias(const float* __restrict__ bq, const float* __restrict__ bk,
                            const float* __restrict__ bv, float* __restrict__ out) {
    int i = blockIdx.x * blockDim.x + threadIdx.x;
    if (i < QKV_COLS)
        out[i] = (i < NH) ? bq[i] : (i < NH + KVH ? bk[i - NH] : bv[i - NH - KVH]);
}

// ---------------------------------------------------------------------------
// Fused: QKV plane + bias + RoPE -> qkv buffer
// ---------------------------------------------------------------------------
__global__ __launch_bounds__(256) void combine_qkv_rope(
    const float* __restrict__ part, const float* __restrict__ bias,
    const int* __restrict__ positions, float* __restrict__ qkv)
{
    __shared__ float row[NH + KVH];
    __shared__ float cs[32], sn[32];
    const int t = blockIdx.x;
    const int tid = threadIdx.x;

    if (tid < 32) {
        int i = tid;
        int pos = positions[t] % S_LEN;
        float freq   = powf(150000.0f, (float)i / 32.0f);
        float interp = 1.0f / (32.0f * freq);
        float extrap = 1.0f / freq;
        float lnT    = logf(150000.0f);
        float low    = 32.0f * logf(4096.0f / (32.0f * 6.2831853071795864f)) / lnT;
        float high   = 32.0f * logf(4096.0f / 6.2831853071795864f) / lnT;
        float ramp   = fminf(fmaxf(((float)i - low) / (high - low), 0.0f), 1.0f);
        float inv    = interp * ramp + extrap * (1.0f - ramp);
        float conc   = 0.1f * logf(32.0f) + 1.0f;
        float tt     = (float)pos * inv;
        cs[i] = cosf(tt) * conc;
        sn[i] = sinf(tt) * conc;
    }

    const float* p0 = part + (size_t)t * QKV_COLS;
    float* orow = qkv + (size_t)t * QKV_COLS;

    for (int c = tid * 4; c < QKV_COLS; c += 256 * 4) {
        float4 a = *(const float4*)(p0 + c);
        float4 bb = *(const float4*)(bias + c);
        float4 r;
        r.x = a.x + bb.x;
        r.y = a.y + bb.y;
        r.z = a.z + bb.z;
        r.w = a.w + bb.w;
        if (c >= NH + KVH) {            // V columns: no rope, write directly
            *(float4*)(orow + c) = r;
        } else {
            *(float4*)(row + c) = r;
        }
    }
    __syncthreads();

    // rope on q (heads 0..63) + k (heads 64..71): 72 heads x 32 rotations
    for (int idx = tid; idx < 72 * 32; idx += 256) {
        int head = idx >> 5, i = idx & 31;
        float x1 = row[head * 64 + i], x2 = row[head * 64 + i + 32];
        orow[head * 64 + i]      = x1 * cs[i] - x2 * sn[i];
        orow[head * 64 + i + 32] = x2 * cs[i] + x1 * sn[i];
    }
}

// combine O split-K partials + bias -> final output [T, 2880]
__global__ void combine_o(const float* __restrict__ part, const float* __restrict__ bo,
                          float* __restrict__ out) {
    const int t = blockIdx.x;
    const float* p0 = part + (size_t)t * OPAD;
    const float* p1 = part + (size_t)T_TOK * OPAD + (size_t)t * OPAD;
    float* o = out + (size_t)t * D_DIM;
    for (int c = threadIdx.x * 4; c < D_DIM; c += 256 * 4) {
        float4 a = *(const float4*)(p0 + c);
        float4 b = *(const float4*)(p1 + c);
        float4 bb = *(const float4*)(bo + c);
        float4 r;
        r.x = a.x + b.x + bb.x;
        r.y = a.y + b.y + bb.y;
        r.z = a.z + b.z + bb.z;
        r.w = a.w + b.w + bb.w;
        *(float4*)(o + c) = r;
    }
}

// ---------------------------------------------------------------------------
// GEMM: 128x128 CTA tile, 256 threads (8 warps of 64x32), 2 CTAs/SM,
// 4-stage cp.async.bulk pipeline (depth-3 prefetch), single fp16 term.
// grid.z = split-K slice: kbase = z*nkc_run, C += z*plane_stride.
// ---------------------------------------------------------------------------
#define STAGE_BYTES 16384
#define NSTAGE      4
#define GEMM_SMEM   (128 + NSTAGE * STAGE_BYTES)

__global__ __launch_bounds__(256, 2) void gemm_tc(
    const __half* __restrict__ Apk, const __half* __restrict__ Bhp,
    float* __restrict__ C,
    int nkc_total, int nkc_run, int Nreal, int ldc, size_t plane_stride)
{
    extern __shared__ __align__(128) uint8_t dsm[];
    const uint32_t base = (uint32_t)__cvta_generic_to_shared(dsm);
    const uint32_t mb = base;
    const uint32_t sdata = base + 128;

    const int tid = threadIdx.x, lane = tid & 31, warp = tid >> 5;
    const int wm = warp >> 2, wn = warp & 3;
    const int mt = blockIdx.y, nt = blockIdx.x;
    const int kbase = blockIdx.z * nkc_run;
    C += (size_t)blockIdx.z * plane_stride;

    if (tid == 0)
#pragma unroll
        for (int s = 0; s < NSTAGE; s++) mbar_init(mb + s * 8, 1);
    __syncthreads();

    const __half* Asrc = Apk + (size_t)mt * nkc_total * 4096 + (size_t)kbase * 4096;
    const __half* Bsrc = Bhp + (size_t)nt * nkc_total * 4096 + (size_t)kbase * 4096;

    float c[4][4][4];
#pragma unroll
    for (int mi = 0; mi < 4; mi++)
#pragma unroll
        for (int ni = 0; ni < 4; ni++)
#pragma unroll
            for (int r = 0; r < 4; r++) c[mi][ni][r] = 0.0f;

    if (tid == 0) {
#pragma unroll
        for (int s = 0; s < 3; s++) {
            uint32_t sb = sdata + s * STAGE_BYTES;
            expect_tx(mb + s * 8, 16384u);
            bulk_g2s(sb,        Asrc + (size_t)s * 4096, 8192, mb + s * 8);
            bulk_g2s(sb + 8192, Bsrc + (size_t)s * 4096, 8192, mb + s * 8);
        }
    }

    const int rA_l = lane & 15;
    const int ckA_l = lane >> 4;
    const int rB_l = (lane & 7) + ((lane >> 4) << 3);
    const int ckB_l = (lane >> 3) & 1;

    for (int i = 0; i < nkc_run; i++) {
        const int s = i & (NSTAGE - 1);
        const int ph = (i >> 2) & 1;
        mbar_wait(mb + s * 8, ph);

        const uint32_t sA = sdata + s * STAGE_BYTES;
        const uint32_t sB = sA + 8192;

#pragma unroll
        for (int ks = 0; ks < 2; ks++) {
            uint32_t a[4][4];
#pragma unroll
            for (int mi = 0; mi < 4; mi++) {
                int r = wm * 64 + mi * 16 + rA_l;
                int ck = ks * 2 + ckA_l;
                ldmx4(a[mi], sA + r * 64 + ((ck ^ ((r >> 1) & 3)) << 4));
            }
            uint32_t b[4][2];
            {
                int ck = ks * 2 + ckB_l;
#pragma unroll
                for (int p = 0; p < 2; p++) {
                    int r = wn * 32 + p * 16 + rB_l;
                    uint32_t d[4];
                    ldmx4(d, sB + r * 64 + ((ck ^ ((r >> 1) & 3)) << 4));
                    b[p * 2][0] = d[0]; b[p * 2][1] = d[1];
                    b[p * 2 + 1][0] = d[2]; b[p * 2 + 1][1] = d[3];
                }
            }
#pragma unroll
            for (int mi = 0; mi < 4; mi++)
#pragma unroll
                for (int ni = 0; ni < 4; ni++) mma16816(c[mi][ni], a[mi], b[ni]);
        }
        __syncthreads();
        if (tid == 0 && i + 3 < nkc_run) {
            const int s2 = (i + 3) & (NSTAGE - 1);
            uint32_t sb = sdata + s2 * STAGE_BYTES;
            expect_tx(mb + s2 * 8, 16384u);
            bulk_g2s(sb,        Asrc + (size_t)(i + 3) * 4096, 8192, mb + s2 * 8);
            bulk_g2s(sb + 8192, Bsrc + (size_t)(i + 3) * 4096, 8192, mb + s2 * 8);
        }
    }

#pragma unroll
    for (int mi = 0; mi < 4; mi++) {
        int row = mt * 128 + wm * 64 + mi * 16 + (lane >> 2);
#pragma unroll
        for (int ni = 0; ni < 4; ni++) {
            int col = nt * 128 + wn * 32 + ni * 8 + (lane & 3) * 2;
            if (col < Nreal) {
                float2 v0 = {c[mi][ni][0], c[mi][ni][1]};
                float2 v1 = {c[mi][ni][2], c[mi][ni][3]};
                *(float2*)(C + (size_t)row * ldc + col) = v0;
                *(float2*)(C + (size_t)(row + 8) * ldc + col) = v1;
            }
        }
    }
}

// ---------------------------------------------------------------------------
// Attention: 4 queries x 1 kv-head per block, 160 threads, K direct to regs
// (no K smem) -> ~45.6KB smem, 3 blocks/SM (reg-limited).
// ---------------------------------------------------------------------------
#define KV_PITCH 66
#define VS_FLOATS 8648    // 131*66 = 8646, padded to multiple of 4
#define ATTN_SMEM ((VS_FLOATS + 2048 + 4 * 160 + 64) * 4)

__global__ __launch_bounds__(160, 3) void attn_kernel(
    const float* __restrict__ qkv, const float* __restrict__ sinks,
    __half* __restrict__ cpk)
{
    extern __shared__ float sm[];
    float* vs   = sm;                          // 131*66 (padded to 8648)
    float* qsm  = vs + VS_FLOATS;              // 2048, 16B-aligned
    float* sc   = qsm + 2048;                  // 4*160
    float* redm = sc + 4 * 160;                // 32
    float* reds = redm + 32;                   // 32

    const int q0  = blockIdx.x * 4;
    const int kh  = blockIdx.y;
    const int b   = blockIdx.z;
    const int tid = threadIdx.x;
    const int lane = tid & 31, w = tid >> 5;
    const int kstartU = (q0 >= 127) ? q0 - 127 : 0;
    const int cntU = q0 + 3 - kstartU + 1;

    for (int i = tid; i < 2048; i += 160) {
        int qq = i >> 9, r = i & 511;
        qsm[r * 4 + qq] = qkv[(size_t)(b * S_LEN + q0 + qq) * QKV_COLS + kh * 512 + r];
    }
    for (int i = tid; i < cntU * 64; i += 160) {
        int r = i >> 6, d = i & 63;
        size_t rb = (size_t)(b * S_LEN + kstartU + r) * QKV_COLS;
        vs[r * KV_PITCH + d] = qkv[rb + 4608 + kh * 64 + d];
    }

    const bool havek = tid < cntU;
    float kreg[64];
    if (havek) {
        const float4* kp = (const float4*)(qkv +
            (size_t)(b * S_LEN + kstartU + tid) * QKV_COLS + 4096 + kh * 64);
#pragma unroll
        for (int u = 0; u < 16; u++) {
            float4 v = kp[u];
            kreg[u * 4 + 0] = v.x; kreg[u * 4 + 1] = v.y;
            kreg[u * 4 + 2] = v.z; kreg[u * 4 + 3] = v.w;
        }
    } else {
#pragma unroll
        for (int d = 0; d < 64; d++) kreg[d] = 0.0f;
    }
    __syncthreads();

    const int kpos = kstartU + tid;

    for (int h8 = 0; h8 < 8; h8++) {
        const float sink = sinks[kh * 8 + h8];
        float s[4] = {-1e30f, -1e30f, -1e30f, -1e30f};
        if (havek) {
            float a0 = 0.f, a1 = 0.f, a2 = 0.f, a3 = 0.f;
            const float4* qp = (const float4*)(qsm + h8 * 256);
#pragma unroll
            for (int d = 0; d < 64; d++) {
                float4 qv = qp[d];
                float kd = kreg[d];
                a0 = fmaf(kd, qv.x, a0);
                a1 = fmaf(kd, qv.y, a1);
                a2 = fmaf(kd, qv.z, a2);
                a3 = fmaf(kd, qv.w, a3);
            }
            float aa[4] = {a0, a1, a2, a3};
#pragma unroll
            for (int qq = 0; qq < 4; qq++) {
                int qg = q0 + qq;
                int loG = qg - 127; if (loG < 0) loG = 0;
                s[qq] = (kpos >= loG && kpos <= qg) ? aa[qq] * 0.125f : -1e30f;
            }
        }
#pragma unroll
        for (int qq = 0; qq < 4; qq++) {
            float m = s[qq];
#pragma unroll
            for (int o = 16; o; o >>= 1) m = fmaxf(m, __shfl_xor_sync(0xffffffffu, m, o));
            if (lane == 0) redm[qq * 8 + w] = m;
        }
        __syncthreads();
        float mq[4], denomq[4];
#pragma unroll
        for (int qq = 0; qq < 4; qq++) {
            float m = redm[qq * 8];
#pragma unroll
            for (int j = 1; j < 5; j++) m = fmaxf(m, redm[qq * 8 + j]);
            mq[qq] = fmaxf(m, sink);
        }
#pragma unroll
        for (int qq = 0; qq < 4; qq++) {
            float p = fexp(s[qq] - mq[qq]);
            sc[qq * 160 + tid] = p;
#pragma unroll
            for (int o = 16; o; o >>= 1) p += __shfl_xor_sync(0xffffffffu, p, o);
            if (lane == 0) reds[qq * 8 + w] = p;
        }
        __syncthreads();
#pragma unroll
        for (int qq = 0; qq < 4; qq++) {
            float sum = reds[qq * 8] + reds[qq * 8 + 1] + reds[qq * 8 + 2] +
                        reds[qq * 8 + 3] + reds[qq * 8 + 4];
            denomq[qq] = sum + fexp(sink - mq[qq]);
        }
        if (w < 4) {
            const int qg = q0 + w;
            int loG = qg - 127; if (loG < 0) loG = 0;
            const int lo = loG - kstartU, hi = qg - kstartU;
            float2 acc = {0.f, 0.f};
            const float* scw = sc + w * 160;
            const float* vb = vs + lane * 2;
            for (int j = lo; j <= hi; j++) {
                float p = scw[j];
                float2 v = *(const float2*)(vb + j * KV_PITCH);
                acc.x = fmaf(p, v.x, acc.x);
                acc.y = fmaf(p, v.y, acc.y);
            }
            float inv = 1.0f / denomq[w];
            int t = b * S_LEN + qg;
            int kcol = (kh * 8 + h8) * 64 + lane * 2;
            size_t o = offP(t, kcol, NKC_O);
            *(__half2*)(cpk + o) = __floats2half2_rn(acc.x * inv, acc.y * inv);
        }
        __syncthreads();
    }
}

// ---------------------------------------------------------------------------
// Launch
// ---------------------------------------------------------------------------
extern "C" void kernel_launch(void* const* d_in, const int* in_sizes, int n_in,
                              void* d_out, int out_size) {
    const float* x     = (const float*)d_in[0];
    const float* wq    = (const float*)d_in[1];
    const float* bq    = (const float*)d_in[2];
    const float* wk    = (const float*)d_in[3];
    const float* bk    = (const float*)d_in[4];
    const float* wv    = (const float*)d_in[5];
    const float* bv    = (const float*)d_in[6];
    const float* wo    = (const float*)d_in[7];
    const float* bo    = (const float*)d_in[8];
    const float* sinks = (const float*)d_in[9];
    const int* positions = (const int*)d_in[10];
    float* out = (float*)d_out;

    void *xpk, *wbh, *wobh, *cpk, *qkv, *qkvp_part, *opart, *biasqkv;
    cudaGetSymbolAddress(&xpk, g_xpk);
    cudaGetSymbolAddress(&wbh, g_wbh);
    cudaGetSymbolAddress(&wobh, g_wobh);
    cudaGetSymbolAddress(&cpk, g_cpk);
    cudaGetSymbolAddress(&qkv, g_qkv);
    cudaGetSymbolAddress(&qkvp_part, g_qkvp);
    cudaGetSymbolAddress(&opart, g_opart);
    cudaGetSymbolAddress(&biasqkv, g_biasqkv);

    float* qkvp = (float*)qkv;
    float* qkvpartp = (float*)qkvp_part;
    float* opartp = (float*)opart;

    cudaFuncSetAttribute(gemm_tc, cudaFuncAttributeMaxDynamicSharedMemorySize, GEMM_SMEM);
    cudaFuncSetAttribute(attn_kernel, cudaFuncAttributeMaxDynamicSharedMemorySize, ATTN_SMEM);

    // 1. pack inputs/weights (single fp16 plane each)
    pack_x<<<dim3(12, T_TOK), 256>>>(x, (__half*)xpk);
    tsp1<<<dim3(128, 90), dim3(32, 8)>>>(wq, (__half*)wbh, D_DIM, NH, NKC_QKV, 0);
    tsp1<<<dim3(16, 90), dim3(32, 8)>>>(wk, (__half*)wbh, D_DIM, KVH, NKC_QKV, NH);
    tsp1<<<dim3(16, 90), dim3(32, 8)>>>(wv, (__half*)wbh, D_DIM, KVH, NKC_QKV, NH + KVH);
    tsp1<<<dim3(92, 128), dim3(32, 8)>>>(wo, (__half*)wobh, NH, D_DIM, NKC_O, 0);
    concat_bias<<<(QKV_COLS + 255) / 256, 256>>>(bq, bk, bv, (float*)biasqkv);

    // 2. QKV projection: full-K single launch, then fused bias+rope pass
    gemm_tc<<<dim3(QKV_COLS / 128, T_TOK / 128, 1), 256, GEMM_SMEM>>>(
        (const __half*)xpk, (const __half*)wbh, qkvpartp,
        NKC_QKV, NKC_QKV, QKV_COLS, QKV_COLS, 0);
    combine_qkv_rope<<<T_TOK, 256>>>(qkvpartp, (const float*)biasqkv, positions, qkvp);

    // 3. attention (writes packed fp16 ctx)
    attn_kernel<<<dim3(S_LEN / 4, 8, B_BATCH), 160, ATTN_SMEM>>>(
        qkvp, sinks, (__half*)cpk);

    // 4. output projection: split-K=2 in one launch (z), then combine (+bias)
    gemm_tc<<<dim3(OPAD / 128, T_TOK / 128, 2), 256, GEMM_SMEM>>>(
        (const __half*)cpk, (const __half*)wobh, opartp,
        NKC_O, NKC_O / 2, OPAD, OPAD, (size_t)T_TOK * OPAD);
    combine_o<<<T_TOK, 256>>>(opartp, bo, out);
}

// round 11
// speedup vs baseline: 1.0305x; 1.0305x over previous
#include <cuda_runtime.h>
#include <cuda_fp16.h>
#include <cstdint>

// ---------------------------------------------------------------------------
// Problem constants
// ---------------------------------------------------------------------------
#define T_TOK   2048
#define D_DIM   2880
#define S_LEN   1024
#define B_BATCH 2
#define WIN     128
#define NH      4096
#define KVH     512
#define QKV_COLS 5120
#define OPAD    2944
#define NKC_QKV 90        // 2880/32
#define NKC_O   128       // 4096/32

// ---------------------------------------------------------------------------
// Scratch
// ---------------------------------------------------------------------------
__device__ __half g_xpk [(size_t)16 * NKC_QKV * 128 * 32];   // x packed fp16 (A blobs)
__device__ __half g_wbh [(size_t)40 * NKC_QKV * 128 * 32];   // qkv weights (B blobs)
__device__ __half g_wobh[(size_t)23 * NKC_O   * 128 * 32];   // wo (B blobs)
__device__ __half g_cpk [(size_t)16 * NKC_O   * 128 * 32];   // ctx packed fp16 (A blobs)
__device__ float  g_qkv  [(size_t)T_TOK * QKV_COLS];
__device__ float  g_qkvp [(size_t)2 * T_TOK * QKV_COLS];     // QKV split-K partials
__device__ float  g_opart[(size_t)2 * T_TOK * OPAD];         // O split-K partials
__device__ float  g_biasqkv[QKV_COLS];

// ---------------------------------------------------------------------------
// Packed layout: 128-row x 32-k tiles, row = 64B, 16B chunks XOR-swizzled by
// ((row>>1)&3) so ldmatrix is conflict-free while bulk copies stay linear.
// ---------------------------------------------------------------------------
__device__ __forceinline__ size_t offP(int r_glob, int k, int nkc) {
    int r = r_glob & 127, ck = (k >> 3) & 3, w = k & 7;
    return ((((size_t)(r_glob >> 7)) * nkc + (k >> 5)) * 128 + r) * 32 +
           (((ck ^ ((r >> 1) & 3)) << 3) + w);
}

// ---------------------------------------------------------------------------
// PTX helpers
// ---------------------------------------------------------------------------
__device__ __forceinline__ void mbar_init(uint32_t a, uint32_t cnt) {
    asm volatile("mbarrier.init.shared.b64 [%0], %1;" :: "r"(a), "r"(cnt) : "memory");
}
__device__ __forceinline__ void mbar_wait(uint32_t a, int ph) {
    uint32_t done = 0;
    while (!done) {
        asm volatile("{\n\t.reg .pred p;\n\t"
                     "mbarrier.try_wait.parity.acquire.cta.shared::cta.b64 p, [%1], %2, 0x989680;\n\t"
                     "selp.b32 %0,1,0,p;\n\t}"
                     : "=r"(done) : "r"(a), "r"((uint32_t)ph) : "memory");
    }
}
__device__ __forceinline__ void expect_tx(uint32_t a, uint32_t bytes) {
    asm volatile("mbarrier.arrive.expect_tx.shared::cta.b64 _, [%0], %1;"
                 :: "r"(a), "r"(bytes) : "memory");
}
__device__ __forceinline__ void bulk_g2s(uint32_t sdst, const void* gsrc,
                                         uint32_t bytes, uint32_t mbar) {
    asm volatile("cp.async.bulk.shared::cluster.global.mbarrier::complete_tx::bytes "
                 "[%0], [%1], %2, [%3];"
                 :: "r"(sdst), "l"(__cvta_generic_to_global(gsrc)), "r"(bytes), "r"(mbar)
                 : "memory");
}
__device__ __forceinline__ void ldmx4(uint32_t* d, uint32_t addr) {
    asm volatile("ldmatrix.sync.aligned.m8n8.x4.shared.b16 {%0,%1,%2,%3}, [%4];"
                 : "=r"(d[0]), "=r"(d[1]), "=r"(d[2]), "=r"(d[3]) : "r"(addr));
}
__device__ __forceinline__ void mma16816(float* c, const uint32_t* a, const uint32_t* b) {
    asm volatile(
        "mma.sync.aligned.m16n8k16.row.col.f32.f16.f16.f32 "
        "{%0,%1,%2,%3},{%4,%5,%6,%7},{%8,%9},{%0,%1,%2,%3};\n"
        : "+f"(c[0]), "+f"(c[1]), "+f"(c[2]), "+f"(c[3])
        : "r"(a[0]), "r"(a[1]), "r"(a[2]), "r"(a[3]), "r"(b[0]), "r"(b[1]));
}

// fast exp on the FMA pipe (x <= 0 path), rel err ~1e-7
__device__ __forceinline__ float fexp(float x) {
    x = fmaxf(x, -87.0f);
    float y = x * 1.44269504f;
    float n = rintf(y);
    float f = y - n;
    float p = 1.33336498e-3f;
    p = fmaf(p, f, 9.61011233e-3f);
    p = fmaf(p, f, 5.55040755e-2f);
    p = fmaf(p, f, 2.40226507e-1f);
    p = fmaf(p, f, 6.93147182e-1f);
    p = fmaf(p, f, 1.0f);
    return p * __int_as_float(((int)n + 127) << 23);
}

// ---------------------------------------------------------------------------
// Prep kernels (vectorized 16B stores into the packed layout)
// ---------------------------------------------------------------------------
__global__ void pack_x(const float* __restrict__ x, __half* __restrict__ o) {
    int idx = blockIdx.x * 256 + threadIdx.x;   // chunk id (8 k each); 360 per row
    int t = blockIdx.y;
    int k = idx * 8;
    if (k < D_DIM) {
        const float* src = x + (size_t)t * D_DIM + k;
        __half h[8];
#pragma unroll
        for (int w = 0; w < 8; w++) h[w] = __float2half_rn(src[w]);
        *(uint4*)(o + offP(t, k, NKC_QKV)) = *(const uint4*)h;
    }
}

// transpose single-plane into packed B layout; one 16B chunk per thread
__global__ void tsp1(const float* __restrict__ in, __half* __restrict__ oh,
                     int R, int C, int nkc, int nbase) {
    __shared__ float tb[32][33];
    int c0 = blockIdx.x * 32, r0 = blockIdx.y * 32;
    int tx = threadIdx.x, ty = threadIdx.y;      // (32, 8)
#pragma unroll
    for (int i = 0; i < 4; i++) {
        int r = r0 + ty + i * 8, c = c0 + tx;
        tb[ty + i * 8][tx] = (c < C) ? in[(size_t)r * C + c] : 0.0f;
    }
    __syncthreads();
    int tid = ty * 32 + tx;
    if (tid < 128) {
        int nn = tid >> 2;          // out row within tile 0..31
        int ck = tid & 3;           // chunk 0..3
        int n = nbase + c0 + nn;
        int k = r0 + ck * 8;
        __half h[8];
#pragma unroll
        for (int w = 0; w < 8; w++)
            h[w] = __float2half_rn(tb[ck * 8 + w][nn]);
        *(uint4*)(oh + offP(n, k, nkc)) = *(const uint4*)h;
    }
}

__global__ void concat_bias(const float* __restrict__ bq, const float* __restrict__ bk,
                            const float* __restrict__ bv, float* __restrict__ out) {
    int i = blockIdx.x * blockDim.x + threadIdx.x;
    if (i < QKV_COLS)
        out[i] = (i < NH) ? bq[i] : (i < NH + KVH ? bk[i - NH] : bv[i - NH - KVH]);
}

// ---------------------------------------------------------------------------
// Fused: combine QKV split-K partials + bias + RoPE -> qkv buffer
// ---------------------------------------------------------------------------
__global__ __launch_bounds__(256) void combine_qkv_rope(
    const float* __restrict__ part, const float* __restrict__ bias,
    const int* __restrict__ positions, float* __restrict__ qkv)
{
    __shared__ float row[NH + KVH];
    __shared__ float cs[32], sn[32];
    const int t = blockIdx.x;
    const int tid = threadIdx.x;

    if (tid < 32) {
        int i = tid;
        int pos = positions[t] % S_LEN;
        float freq   = powf(150000.0f, (float)i / 32.0f);
        float interp = 1.0f / (32.0f * freq);
        float extrap = 1.0f / freq;
        float lnT    = logf(150000.0f);
        float low    = 32.0f * logf(4096.0f / (32.0f * 6.2831853071795864f)) / lnT;
        float high   = 32.0f * logf(4096.0f / 6.2831853071795864f) / lnT;
        float ramp   = fminf(fmaxf(((float)i - low) / (high - low), 0.0f), 1.0f);
        float inv    = interp * ramp + extrap * (1.0f - ramp);
        float conc   = 0.1f * logf(32.0f) + 1.0f;
        float tt     = (float)pos * inv;
        cs[i] = cosf(tt) * conc;
        sn[i] = sinf(tt) * conc;
    }

    const float* p0 = part + (size_t)t * QKV_COLS;
    const float* p1 = part + (size_t)T_TOK * QKV_COLS + (size_t)t * QKV_COLS;
    float* orow = qkv + (size_t)t * QKV_COLS;

    for (int c = tid * 4; c < QKV_COLS; c += 256 * 4) {
        float4 a = *(const float4*)(p0 + c);
        float4 b = *(const float4*)(p1 + c);
        float4 bb = *(const float4*)(bias + c);
        float4 r;
        r.x = a.x + b.x + bb.x;
        r.y = a.y + b.y + bb.y;
        r.z = a.z + b.z + bb.z;
        r.w = a.w + b.w + bb.w;
        if (c >= NH + KVH) {            // V columns: no rope, write directly
            *(float4*)(orow + c) = r;
        } else {
            *(float4*)(row + c) = r;
        }
    }
    __syncthreads();

    for (int idx = tid; idx < 72 * 32; idx += 256) {
        int head = idx >> 5, i = idx & 31;
        float x1 = row[head * 64 + i], x2 = row[head * 64 + i + 32];
        orow[head * 64 + i]      = x1 * cs[i] - x2 * sn[i];
        orow[head * 64 + i + 32] = x2 * cs[i] + x1 * sn[i];
    }
}

// combine O split-K partials + bias -> final output [T, 2880]
__global__ void combine_o(const float* __restrict__ part, const float* __restrict__ bo,
                          float* __restrict__ out) {
    const int t = blockIdx.x;
    const float* p0 = part + (size_t)t * OPAD;
    const float* p1 = part + (size_t)T_TOK * OPAD + (size_t)t * OPAD;
    float* o = out + (size_t)t * D_DIM;
    for (int c = threadIdx.x * 4; c < D_DIM; c += 256 * 4) {
        float4 a = *(const float4*)(p0 + c);
        float4 b = *(const float4*)(p1 + c);
        float4 bb = *(const float4*)(bo + c);
        float4 r;
        r.x = a.x + b.x + bb.x;
        r.y = a.y + b.y + bb.y;
        r.z = a.z + b.z + bb.z;
        r.w = a.w + b.w + bb.w;
        *(float4*)(o + c) = r;
    }
}

// ---------------------------------------------------------------------------
// GEMM: 128x128 CTA tile, 256 threads (8 warps of 64x32), 2 CTAs/SM,
// 4-stage cp.async.bulk pipeline (depth-3 prefetch), single fp16 term.
// grid.z = split-K slice: kbase = z*nkc_run, C += z*plane_stride.
// ---------------------------------------------------------------------------
#define STAGE_BYTES 16384
#define NSTAGE      4
#define GEMM_SMEM   (128 + NSTAGE * STAGE_BYTES)

__global__ __launch_bounds__(256, 2) void gemm_tc(
    const __half* __restrict__ Apk, const __half* __restrict__ Bhp,
    float* __restrict__ C,
    int nkc_total, int nkc_run, int Nreal, int ldc, size_t plane_stride)
{
    extern __shared__ __align__(128) uint8_t dsm[];
    const uint32_t base = (uint32_t)__cvta_generic_to_shared(dsm);
    const uint32_t mb = base;
    const uint32_t sdata = base + 128;

    const int tid = threadIdx.x, lane = tid & 31, warp = tid >> 5;
    const int wm = warp >> 2, wn = warp & 3;
    const int mt = blockIdx.y, nt = blockIdx.x;
    const int kbase = blockIdx.z * nkc_run;
    C += (size_t)blockIdx.z * plane_stride;

    if (tid == 0)
#pragma unroll
        for (int s = 0; s < NSTAGE; s++) mbar_init(mb + s * 8, 1);
    __syncthreads();

    const __half* Asrc = Apk + (size_t)mt * nkc_total * 4096 + (size_t)kbase * 4096;
    const __half* Bsrc = Bhp + (size_t)nt * nkc_total * 4096 + (size_t)kbase * 4096;

    float c[4][4][4];
#pragma unroll
    for (int mi = 0; mi < 4; mi++)
#pragma unroll
        for (int ni = 0; ni < 4; ni++)
#pragma unroll
            for (int r = 0; r < 4; r++) c[mi][ni][r] = 0.0f;

    if (tid == 0) {
#pragma unroll
        for (int s = 0; s < 3; s++) {
            uint32_t sb = sdata + s * STAGE_BYTES;
            expect_tx(mb + s * 8, 16384u);
            bulk_g2s(sb,        Asrc + (size_t)s * 4096, 8192, mb + s * 8);
            bulk_g2s(sb + 8192, Bsrc + (size_t)s * 4096, 8192, mb + s * 8);
        }
    }

    const int rA_l = lane & 15;
    const int ckA_l = lane >> 4;
    const int rB_l = (lane & 7) + ((lane >> 4) << 3);
    const int ckB_l = (lane >> 3) & 1;

    for (int i = 0; i < nkc_run; i++) {
        const int s = i & (NSTAGE - 1);
        const int ph = (i >> 2) & 1;
        mbar_wait(mb + s * 8, ph);

        const uint32_t sA = sdata + s * STAGE_BYTES;
        const uint32_t sB = sA + 8192;

#pragma unroll
        for (int ks = 0; ks < 2; ks++) {
            uint32_t a[4][4];
#pragma unroll
            for (int mi = 0; mi < 4; mi++) {
                int r = wm * 64 + mi * 16 + rA_l;
                int ck = ks * 2 + ckA_l;
                ldmx4(a[mi], sA + r * 64 + ((ck ^ ((r >> 1) & 3)) << 4));
            }
            uint32_t b[4][2];
            {
                int ck = ks * 2 + ckB_l;
#pragma unroll
                for (int p = 0; p < 2; p++) {
                    int r = wn * 32 + p * 16 + rB_l;
                    uint32_t d[4];
                    ldmx4(d, sB + r * 64 + ((ck ^ ((r >> 1) & 3)) << 4));
                    b[p * 2][0] = d[0]; b[p * 2][1] = d[1];
                    b[p * 2 + 1][0] = d[2]; b[p * 2 + 1][1] = d[3];
                }
            }
#pragma unroll
            for (int mi = 0; mi < 4; mi++)
#pragma unroll
                for (int ni = 0; ni < 4; ni++) mma16816(c[mi][ni], a[mi], b[ni]);
        }
        __syncthreads();
        if (tid == 0 && i + 3 < nkc_run) {
            const int s2 = (i + 3) & (NSTAGE - 1);
            uint32_t sb = sdata + s2 * STAGE_BYTES;
            expect_tx(mb + s2 * 8, 16384u);
            bulk_g2s(sb,        Asrc + (size_t)(i + 3) * 4096, 8192, mb + s2 * 8);
            bulk_g2s(sb + 8192, Bsrc + (size_t)(i + 3) * 4096, 8192, mb + s2 * 8);
        }
    }

#pragma unroll
    for (int mi = 0; mi < 4; mi++) {
        int row = mt * 128 + wm * 64 + mi * 16 + (lane >> 2);
#pragma unroll
        for (int ni = 0; ni < 4; ni++) {
            int col = nt * 128 + wn * 32 + ni * 8 + (lane & 3) * 2;
            if (col < Nreal) {
                float2 v0 = {c[mi][ni][0], c[mi][ni][1]};
                float2 v1 = {c[mi][ni][2], c[mi][ni][3]};
                *(float2*)(C + (size_t)row * ldc + col) = v0;
                *(float2*)(C + (size_t)(row + 8) * ldc + col) = v1;
            }
        }
    }
}

// ---------------------------------------------------------------------------
// Attention: 4 queries x 1 kv-head per block, 160 threads, K direct to regs
// (no K smem) -> ~45.6KB smem, 3 blocks/SM (reg-limited).
// ---------------------------------------------------------------------------
#define KV_PITCH 66
#define VS_FLOATS 8648    // 131*66 = 8646, padded to multiple of 4
#define ATTN_SMEM ((VS_FLOATS + 2048 + 4 * 160 + 64) * 4)

__global__ __launch_bounds__(160, 3) void attn_kernel(
    const float* __restrict__ qkv, const float* __restrict__ sinks,
    __half* __restrict__ cpk)
{
    extern __shared__ float sm[];
    float* vs   = sm;                          // 131*66 (padded to 8648)
    float* qsm  = vs + VS_FLOATS;              // 2048, 16B-aligned
    float* sc   = qsm + 2048;                  // 4*160
    float* redm = sc + 4 * 160;                // 32
    float* reds = redm + 32;                   // 32

    const int q0  = blockIdx.x * 4;
    const int kh  = blockIdx.y;
    const int b   = blockIdx.z;
    const int tid = threadIdx.x;
    const int lane = tid & 31, w = tid >> 5;
    const int kstartU = (q0 >= 127) ? q0 - 127 : 0;
    const int cntU = q0 + 3 - kstartU + 1;

    for (int i = tid; i < 2048; i += 160) {
        int qq = i >> 9, r = i & 511;
        qsm[r * 4 + qq] = qkv[(size_t)(b * S_LEN + q0 + qq) * QKV_COLS + kh * 512 + r];
    }
    for (int i = tid; i < cntU * 64; i += 160) {
        int r = i >> 6, d = i & 63;
        size_t rb = (size_t)(b * S_LEN + kstartU + r) * QKV_COLS;
        vs[r * KV_PITCH + d] = qkv[rb + 4608 + kh * 64 + d];
    }

    const bool havek = tid < cntU;
    float kreg[64];
    if (havek) {
        const float4* kp = (const float4*)(qkv +
            (size_t)(b * S_LEN + kstartU + tid) * QKV_COLS + 4096 + kh * 64);
#pragma unroll
        for (int u = 0; u < 16; u++) {
            float4 v = kp[u];
            kreg[u * 4 + 0] = v.x; kreg[u * 4 + 1] = v.y;
            kreg[u * 4 + 2] = v.z; kreg[u * 4 + 3] = v.w;
        }
    } else {
#pragma unroll
        for (int d = 0; d < 64; d++) kreg[d] = 0.0f;
    }
    __syncthreads();

    const int kpos = kstartU + tid;

    for (int h8 = 0; h8 < 8; h8++) {
        const float sink = sinks[kh * 8 + h8];
        float s[4] = {-1e30f, -1e30f, -1e30f, -1e30f};
        if (havek) {
            float a0 = 0.f, a1 = 0.f, a2 = 0.f, a3 = 0.f;
            const float4* qp = (const float4*)(qsm + h8 * 256);
#pragma unroll
            for (int d = 0; d < 64; d++) {
                float4 qv = qp[d];
                float kd = kreg[d];
                a0 = fmaf(kd, qv.x, a0);
                a1 = fmaf(kd, qv.y, a1);
                a2 = fmaf(kd, qv.z, a2);
                a3 = fmaf(kd, qv.w, a3);
            }
            float aa[4] = {a0, a1, a2, a3};
#pragma unroll
            for (int qq = 0; qq < 4; qq++) {
                int qg = q0 + qq;
                int loG = qg - 127; if (loG < 0) loG = 0;
                s[qq] = (kpos >= loG && kpos <= qg) ? aa[qq] * 0.125f : -1e30f;
            }
        }
#pragma unroll
        for (int qq = 0; qq < 4; qq++) {
            float m = s[qq];
#pragma unroll
            for (int o = 16; o; o >>= 1) m = fmaxf(m, __shfl_xor_sync(0xffffffffu, m, o));
            if (lane == 0) redm[qq * 8 + w] = m;
        }
        __syncthreads();
        float mq[4], denomq[4];
#pragma unroll
        for (int qq = 0; qq < 4; qq++) {
            float m = redm[qq * 8];
#pragma unroll
            for (int j = 1; j < 5; j++) m = fmaxf(m, redm[qq * 8 + j]);
            mq[qq] = fmaxf(m, sink);
        }
#pragma unroll
        for (int qq = 0; qq < 4; qq++) {
            float p = fexp(s[qq] - mq[qq]);
            sc[qq * 160 + tid] = p;
#pragma unroll
            for (int o = 16; o; o >>= 1) p += __shfl_xor_sync(0xffffffffu, p, o);
            if (lane == 0) reds[qq * 8 + w] = p;
        }
        __syncthreads();
#pragma unroll
        for (int qq = 0; qq < 4; qq++) {
            float sum = reds[qq * 8] + reds[qq * 8 + 1] + reds[qq * 8 + 2] +
                        reds[qq * 8 + 3] + reds[qq * 8 + 4];
            denomq[qq] = sum + fexp(sink - mq[qq]);
        }
        if (w < 4) {
            const int qg = q0 + w;
            int loG = qg - 127; if (loG < 0) loG = 0;
            const int lo = loG - kstartU, hi = qg - kstartU;
            float2 acc = {0.f, 0.f};
            const float* scw = sc + w * 160;
            const float* vb = vs + lane * 2;
            for (int j = lo; j <= hi; j++) {
                float p = scw[j];
                float2 v = *(const float2*)(vb + j * KV_PITCH);
                acc.x = fmaf(p, v.x, acc.x);
                acc.y = fmaf(p, v.y, acc.y);
            }
            float inv = 1.0f / denomq[w];
            int t = b * S_LEN + qg;
            int kcol = (kh * 8 + h8) * 64 + lane * 2;
            size_t o = offP(t, kcol, NKC_O);
            *(__half2*)(cpk + o) = __floats2half2_rn(acc.x * inv, acc.y * inv);
        }
        __syncthreads();
    }
}

// ---------------------------------------------------------------------------
// Launch
// ---------------------------------------------------------------------------
extern "C" void kernel_launch(void* const* d_in, const int* in_sizes, int n_in,
                              void* d_out, int out_size) {
    const float* x     = (const float*)d_in[0];
    const float* wq    = (const float*)d_in[1];
    const float* bq    = (const float*)d_in[2];
    const float* wk    = (const float*)d_in[3];
    const float* bk    = (const float*)d_in[4];
    const float* wv    = (const float*)d_in[5];
    const float* bv    = (const float*)d_in[6];
    const float* wo    = (const float*)d_in[7];
    const float* bo    = (const float*)d_in[8];
    const float* sinks = (const float*)d_in[9];
    const int* positions = (const int*)d_in[10];
    float* out = (float*)d_out;

    void *xpk, *wbh, *wobh, *cpk, *qkv, *qkvp_part, *opart, *biasqkv;
    cudaGetSymbolAddress(&xpk, g_xpk);
    cudaGetSymbolAddress(&wbh, g_wbh);
    cudaGetSymbolAddress(&wobh, g_wobh);
    cudaGetSymbolAddress(&cpk, g_cpk);
    cudaGetSymbolAddress(&qkv, g_qkv);
    cudaGetSymbolAddress(&qkvp_part, g_qkvp);
    cudaGetSymbolAddress(&opart, g_opart);
    cudaGetSymbolAddress(&biasqkv, g_biasqkv);

    float* qkvp = (float*)qkv;
    float* qkvpartp = (float*)qkvp_part;
    float* opartp = (float*)opart;

    cudaFuncSetAttribute(gemm_tc, cudaFuncAttributeMaxDynamicSharedMemorySize, GEMM_SMEM);
    cudaFuncSetAttribute(attn_kernel, cudaFuncAttributeMaxDynamicSharedMemorySize, ATTN_SMEM);

    // 1. pack inputs/weights (single fp16 plane each, 16B vectorized stores)
    pack_x<<<dim3(2, T_TOK), 256>>>(x, (__half*)xpk);
    tsp1<<<dim3(128, 90), dim3(32, 8)>>>(wq, (__half*)wbh, D_DIM, NH, NKC_QKV, 0);
    tsp1<<<dim3(16, 90), dim3(32, 8)>>>(wk, (__half*)wbh, D_DIM, KVH, NKC_QKV, NH);
    tsp1<<<dim3(16, 90), dim3(32, 8)>>>(wv, (__half*)wbh, D_DIM, KVH, NKC_QKV, NH + KVH);
    tsp1<<<dim3(92, 128), dim3(32, 8)>>>(wo, (__half*)wobh, NH, D_DIM, NKC_O, 0);
    concat_bias<<<(QKV_COLS + 255) / 256, 256>>>(bq, bk, bv, (float*)biasqkv);

    // 2. QKV projection: split-K=2 in one launch (z), then fused combine+rope
    gemm_tc<<<dim3(QKV_COLS / 128, T_TOK / 128, 2), 256, GEMM_SMEM>>>(
        (const __half*)xpk, (const __half*)wbh, qkvpartp,
        NKC_QKV, NKC_QKV / 2, QKV_COLS, QKV_COLS, (size_t)T_TOK * QKV_COLS);
    combine_qkv_rope<<<T_TOK, 256>>>(qkvpartp, (const float*)biasqkv, positions, qkvp);

    // 3. attention (writes packed fp16 ctx)
    attn_kernel<<<dim3(S_LEN / 4, 8, B_BATCH), 160, ATTN_SMEM>>>(
        qkvp, sinks, (__half*)cpk);

    // 4. output projection: split-K=2 in one launch (z), then combine (+bias)
    gemm_tc<<<dim3(OPAD / 128, T_TOK / 128, 2), 256, GEMM_SMEM>>>(
        (const __half*)cpk, (const __half*)wobh, opartp,
        NKC_O, NKC_O / 2, OPAD, OPAD, (size_t)T_TOK * OPAD);
    combine_o<<<T_TOK, 256>>>(opartp, bo, out);
}

// round 12
// speedup vs baseline: 1.0401x; 1.0093x over previous
#include <cuda_runtime.h>
#include <cuda_fp16.h>
#include <cstdint>

// ---------------------------------------------------------------------------
// Problem constants
// ---------------------------------------------------------------------------
#define T_TOK   2048
#define D_DIM   2880
#define S_LEN   1024
#define B_BATCH 2
#define WIN     128
#define NH      4096
#define KVH     512
#define QKV_COLS 5120
#define OPAD    2944
#define NKC_QKV 90        // 2880/32
#define NKC_O   128       // 4096/32

// ---------------------------------------------------------------------------
// Scratch
// ---------------------------------------------------------------------------
__device__ __half g_xpk [(size_t)16 * NKC_QKV * 128 * 32];   // x packed fp16 (A blobs)
__device__ __half g_wbh [(size_t)40 * NKC_QKV * 128 * 32];   // qkv weights (B blobs)
__device__ __half g_wobh[(size_t)23 * NKC_O   * 128 * 32];   // wo (B blobs)
__device__ __half g_cpk [(size_t)16 * NKC_O   * 128 * 32];   // ctx packed fp16 (A blobs)
__device__ float  g_qkv  [(size_t)T_TOK * QKV_COLS];
__device__ float  g_qkvp [(size_t)2 * T_TOK * QKV_COLS];     // QKV split-K partials
__device__ float  g_opart[(size_t)2 * T_TOK * OPAD];         // O split-K partials
__device__ float  g_biasqkv[QKV_COLS];

// ---------------------------------------------------------------------------
// Packed layout: 128-row x 32-k tiles, row = 64B, 16B chunks XOR-swizzled by
// ((row>>1)&3) so ldmatrix is conflict-free while bulk copies stay linear.
// ---------------------------------------------------------------------------
__device__ __forceinline__ size_t offP(int r_glob, int k, int nkc) {
    int r = r_glob & 127, ck = (k >> 3) & 3, w = k & 7;
    return ((((size_t)(r_glob >> 7)) * nkc + (k >> 5)) * 128 + r) * 32 +
           (((ck ^ ((r >> 1) & 3)) << 3) + w);
}

// ---------------------------------------------------------------------------
// PTX helpers
// ---------------------------------------------------------------------------
__device__ __forceinline__ void mbar_init(uint32_t a, uint32_t cnt) {
    asm volatile("mbarrier.init.shared.b64 [%0], %1;" :: "r"(a), "r"(cnt) : "memory");
}
__device__ __forceinline__ void mbar_wait(uint32_t a, int ph) {
    uint32_t done = 0;
    while (!done) {
        asm volatile("{\n\t.reg .pred p;\n\t"
                     "mbarrier.try_wait.parity.acquire.cta.shared::cta.b64 p, [%1], %2, 0x989680;\n\t"
                     "selp.b32 %0,1,0,p;\n\t}"
                     : "=r"(done) : "r"(a), "r"((uint32_t)ph) : "memory");
    }
}
__device__ __forceinline__ void expect_tx(uint32_t a, uint32_t bytes) {
    asm volatile("mbarrier.arrive.expect_tx.shared::cta.b64 _, [%0], %1;"
                 :: "r"(a), "r"(bytes) : "memory");
}
__device__ __forceinline__ void bulk_g2s(uint32_t sdst, const void* gsrc,
                                         uint32_t bytes, uint32_t mbar) {
    asm volatile("cp.async.bulk.shared::cluster.global.mbarrier::complete_tx::bytes "
                 "[%0], [%1], %2, [%3];"
                 :: "r"(sdst), "l"(__cvta_generic_to_global(gsrc)), "r"(bytes), "r"(mbar)
                 : "memory");
}
__device__ __forceinline__ void ldmx4(uint32_t* d, uint32_t addr) {
    asm volatile("ldmatrix.sync.aligned.m8n8.x4.shared.b16 {%0,%1,%2,%3}, [%4];"
                 : "=r"(d[0]), "=r"(d[1]), "=r"(d[2]), "=r"(d[3]) : "r"(addr));
}
__device__ __forceinline__ void mma16816(float* c, const uint32_t* a, const uint32_t* b) {
    asm volatile(
        "mma.sync.aligned.m16n8k16.row.col.f32.f16.f16.f32 "
        "{%0,%1,%2,%3},{%4,%5,%6,%7},{%8,%9},{%0,%1,%2,%3};\n"
        : "+f"(c[0]), "+f"(c[1]), "+f"(c[2]), "+f"(c[3])
        : "r"(a[0]), "r"(a[1]), "r"(a[2]), "r"(a[3]), "r"(b[0]), "r"(b[1]));
}

// fast exp on the FMA pipe (x <= 0 path), rel err ~1e-7
__device__ __forceinline__ float fexp(float x) {
    x = fmaxf(x, -87.0f);
    float y = x * 1.44269504f;
    float n = rintf(y);
    float f = y - n;
    float p = 1.33336498e-3f;
    p = fmaf(p, f, 9.61011233e-3f);
    p = fmaf(p, f, 5.55040755e-2f);
    p = fmaf(p, f, 2.40226507e-1f);
    p = fmaf(p, f, 6.93147182e-1f);
    p = fmaf(p, f, 1.0f);
    return p * __int_as_float(((int)n + 127) << 23);
}

// ---------------------------------------------------------------------------
// Prep kernels v2 — wide contiguous access
// ---------------------------------------------------------------------------
// pack_x: NOT a transpose. One warp = 8 t-rows x one 32-k tile.
// Loads: 8 rows x 128B coalesced. Stores: 8 rows x 64B = 512B contiguous.
__global__ void pack_x(const float* __restrict__ x, __half* __restrict__ o) {
    int gw = (blockIdx.x * blockDim.x + threadIdx.x) >> 5;
    int lane = threadIdx.x & 31;
    int kt = gw % NKC_QKV;
    int tb = gw / NKC_QKV;
    if (tb >= T_TOK / 8) return;
    int j = lane >> 2, c = lane & 3;
    int t = tb * 8 + j;
    int k = kt * 32 + c * 8;
    const float* src = x + (size_t)t * D_DIM + k;
    float4 v0 = *(const float4*)src;
    float4 v1 = *(const float4*)(src + 4);
    __half h[8];
    h[0] = __float2half_rn(v0.x); h[1] = __float2half_rn(v0.y);
    h[2] = __float2half_rn(v0.z); h[3] = __float2half_rn(v0.w);
    h[4] = __float2half_rn(v1.x); h[5] = __float2half_rn(v1.y);
    h[6] = __float2half_rn(v1.z); h[7] = __float2half_rn(v1.w);
    *(uint4*)(o + offP(t, k, NKC_QKV)) = *(const uint4*)h;
}

// tsp1: 64x64 transpose tiles, (32,8) threads, 16 loads/thread (MLP 16),
// stores grouped so each warp half writes 512B contiguous runs.
__global__ void tsp1(const float* __restrict__ in, __half* __restrict__ oh,
                     int R, int C, int nkc, int nbase) {
    __shared__ float tb[64][65];
    int c0 = blockIdx.x * 64, r0 = blockIdx.y * 64;
    int tx = threadIdx.x, ty = threadIdx.y;      // (32, 8)
#pragma unroll
    for (int i = 0; i < 8; i++) {
        int r = r0 + ty + i * 8;
#pragma unroll
        for (int cc = 0; cc < 2; cc++) {
            int c = c0 + cc * 32 + tx;
            tb[ty + i * 8][cc * 32 + tx] = (c < C) ? in[(size_t)r * C + c] : 0.0f;
        }
    }
    __syncthreads();
    int tid = ty * 32 + tx;
    int nrow = tid >> 2;        // 0..63 output row within tile
    int ckg = tid & 3;          // chunk group
    int n = nbase + c0 + nrow;
#pragma unroll
    for (int half = 0; half < 2; half++) {
        int ck = ckg + half * 4;        // 0..7 (two k-tiles of 32)
        int k = r0 + ck * 8;
        __half h[8];
#pragma unroll
        for (int w = 0; w < 8; w++)
            h[w] = __float2half_rn(tb[ck * 8 + w][nrow]);
        *(uint4*)(oh + offP(n, k, nkc)) = *(const uint4*)h;
    }
}

__global__ void concat_bias(const float* __restrict__ bq, const float* __restrict__ bk,
                            const float* __restrict__ bv, float* __restrict__ out) {
    int i = blockIdx.x * blockDim.x + threadIdx.x;
    if (i < QKV_COLS)
        out[i] = (i < NH) ? bq[i] : (i < NH + KVH ? bk[i - NH] : bv[i - NH - KVH]);
}

// ---------------------------------------------------------------------------
// Fused: combine QKV split-K partials + bias + RoPE -> qkv buffer
// ---------------------------------------------------------------------------
__global__ __launch_bounds__(256) void combine_qkv_rope(
    const float* __restrict__ part, const float* __restrict__ bias,
    const int* __restrict__ positions, float* __restrict__ qkv)
{
    __shared__ float row[NH + KVH];
    __shared__ float cs[32], sn[32];
    const int t = blockIdx.x;
    const int tid = threadIdx.x;

    if (tid < 32) {
        int i = tid;
        int pos = positions[t] % S_LEN;
        float freq   = powf(150000.0f, (float)i / 32.0f);
        float interp = 1.0f / (32.0f * freq);
        float extrap = 1.0f / freq;
        float lnT    = logf(150000.0f);
        float low    = 32.0f * logf(4096.0f / (32.0f * 6.2831853071795864f)) / lnT;
        float high   = 32.0f * logf(4096.0f / 6.2831853071795864f) / lnT;
        float ramp   = fminf(fmaxf(((float)i - low) / (high - low), 0.0f), 1.0f);
        float inv    = interp * ramp + extrap * (1.0f - ramp);
        float conc   = 0.1f * logf(32.0f) + 1.0f;
        float tt     = (float)pos * inv;
        cs[i] = cosf(tt) * conc;
        sn[i] = sinf(tt) * conc;
    }

    const float* p0 = part + (size_t)t * QKV_COLS;
    const float* p1 = part + (size_t)T_TOK * QKV_COLS + (size_t)t * QKV_COLS;
    float* orow = qkv + (size_t)t * QKV_COLS;

    for (int c = tid * 4; c < QKV_COLS; c += 256 * 4) {
        float4 a = *(const float4*)(p0 + c);
        float4 b = *(const float4*)(p1 + c);
        float4 bb = *(const float4*)(bias + c);
        float4 r;
        r.x = a.x + b.x + bb.x;
        r.y = a.y + b.y + bb.y;
        r.z = a.z + b.z + bb.z;
        r.w = a.w + b.w + bb.w;
        if (c >= NH + KVH) {            // V columns: no rope, write directly
            *(float4*)(orow + c) = r;
        } else {
            *(float4*)(row + c) = r;
        }
    }
    __syncthreads();

    for (int idx = tid; idx < 72 * 32; idx += 256) {
        int head = idx >> 5, i = idx & 31;
        float x1 = row[head * 64 + i], x2 = row[head * 64 + i + 32];
        orow[head * 64 + i]      = x1 * cs[i] - x2 * sn[i];
        orow[head * 64 + i + 32] = x2 * cs[i] + x1 * sn[i];
    }
}

// combine O split-K partials + bias -> final output [T, 2880]
__global__ void combine_o(const float* __restrict__ part, const float* __restrict__ bo,
                          float* __restrict__ out) {
    const int t = blockIdx.x;
    const float* p0 = part + (size_t)t * OPAD;
    const float* p1 = part + (size_t)T_TOK * OPAD + (size_t)t * OPAD;
    float* o = out + (size_t)t * D_DIM;
    for (int c = threadIdx.x * 4; c < D_DIM; c += 256 * 4) {
        float4 a = *(const float4*)(p0 + c);
        float4 b = *(const float4*)(p1 + c);
        float4 bb = *(const float4*)(bo + c);
        float4 r;
        r.x = a.x + b.x + bb.x;
        r.y = a.y + b.y + bb.y;
        r.z = a.z + b.z + bb.z;
        r.w = a.w + b.w + bb.w;
        *(float4*)(o + c) = r;
    }
}

// ---------------------------------------------------------------------------
// GEMM: 128x128 CTA tile, 256 threads (8 warps of 64x32), 2 CTAs/SM,
// 4-stage cp.async.bulk pipeline (depth-3 prefetch), single fp16 term.
// grid.z = split-K slice: kbase = z*nkc_run, C += z*plane_stride.
// ---------------------------------------------------------------------------
#define STAGE_BYTES 16384
#define NSTAGE      4
#define GEMM_SMEM   (128 + NSTAGE * STAGE_BYTES)

__global__ __launch_bounds__(256, 2) void gemm_tc(
    const __half* __restrict__ Apk, const __half* __restrict__ Bhp,
    float* __restrict__ C,
    int nkc_total, int nkc_run, int Nreal, int ldc, size_t plane_stride)
{
    extern __shared__ __align__(128) uint8_t dsm[];
    const uint32_t base = (uint32_t)__cvta_generic_to_shared(dsm);
    const uint32_t mb = base;
    const uint32_t sdata = base + 128;

    const int tid = threadIdx.x, lane = tid & 31, warp = tid >> 5;
    const int wm = warp >> 2, wn = warp & 3;
    const int mt = blockIdx.y, nt = blockIdx.x;
    const int kbase = blockIdx.z * nkc_run;
    C += (size_t)blockIdx.z * plane_stride;

    if (tid == 0)
#pragma unroll
        for (int s = 0; s < NSTAGE; s++) mbar_init(mb + s * 8, 1);
    __syncthreads();

    const __half* Asrc = Apk + (size_t)mt * nkc_total * 4096 + (size_t)kbase * 4096;
    const __half* Bsrc = Bhp + (size_t)nt * nkc_total * 4096 + (size_t)kbase * 4096;

    float c[4][4][4];
#pragma unroll
    for (int mi = 0; mi < 4; mi++)
#pragma unroll
        for (int ni = 0; ni < 4; ni++)
#pragma unroll
            for (int r = 0; r < 4; r++) c[mi][ni][r] = 0.0f;

    if (tid == 0) {
#pragma unroll
        for (int s = 0; s < 3; s++) {
            uint32_t sb = sdata + s * STAGE_BYTES;
            expect_tx(mb + s * 8, 16384u);
            bulk_g2s(sb,        Asrc + (size_t)s * 4096, 8192, mb + s * 8);
            bulk_g2s(sb + 8192, Bsrc + (size_t)s * 4096, 8192, mb + s * 8);
        }
    }

    const int rA_l = lane & 15;
    const int ckA_l = lane >> 4;
    const int rB_l = (lane & 7) + ((lane >> 4) << 3);
    const int ckB_l = (lane >> 3) & 1;

    for (int i = 0; i < nkc_run; i++) {
        const int s = i & (NSTAGE - 1);
        const int ph = (i >> 2) & 1;
        mbar_wait(mb + s * 8, ph);

        const uint32_t sA = sdata + s * STAGE_BYTES;
        const uint32_t sB = sA + 8192;

#pragma unroll
        for (int ks = 0; ks < 2; ks++) {
            uint32_t a[4][4];
#pragma unroll
            for (int mi = 0; mi < 4; mi++) {
                int r = wm * 64 + mi * 16 + rA_l;
                int ck = ks * 2 + ckA_l;
                ldmx4(a[mi], sA + r * 64 + ((ck ^ ((r >> 1) & 3)) << 4));
            }
            uint32_t b[4][2];
            {
                int ck = ks * 2 + ckB_l;
#pragma unroll
                for (int p = 0; p < 2; p++) {
                    int r = wn * 32 + p * 16 + rB_l;
                    uint32_t d[4];
                    ldmx4(d, sB + r * 64 + ((ck ^ ((r >> 1) & 3)) << 4));
                    b[p * 2][0] = d[0]; b[p * 2][1] = d[1];
                    b[p * 2 + 1][0] = d[2]; b[p * 2 + 1][1] = d[3];
                }
            }
#pragma unroll
            for (int mi = 0; mi < 4; mi++)
#pragma unroll
                for (int ni = 0; ni < 4; ni++) mma16816(c[mi][ni], a[mi], b[ni]);
        }
        __syncthreads();
        if (tid == 0 && i + 3 < nkc_run) {
            const int s2 = (i + 3) & (NSTAGE - 1);
            uint32_t sb = sdata + s2 * STAGE_BYTES;
            expect_tx(mb + s2 * 8, 16384u);
            bulk_g2s(sb,        Asrc + (size_t)(i + 3) * 4096, 8192, mb + s2 * 8);
            bulk_g2s(sb + 8192, Bsrc + (size_t)(i + 3) * 4096, 8192, mb + s2 * 8);
        }
    }

#pragma unroll
    for (int mi = 0; mi < 4; mi++) {
        int row = mt * 128 + wm * 64 + mi * 16 + (lane >> 2);
#pragma unroll
        for (int ni = 0; ni < 4; ni++) {
            int col = nt * 128 + wn * 32 + ni * 8 + (lane & 3) * 2;
            if (col < Nreal) {
                float2 v0 = {c[mi][ni][0], c[mi][ni][1]};
                float2 v1 = {c[mi][ni][2], c[mi][ni][3]};
                *(float2*)(C + (size_t)row * ldc + col) = v0;
                *(float2*)(C + (size_t)(row + 8) * ldc + col) = v1;
            }
        }
    }
}

// ---------------------------------------------------------------------------
// Attention: 4 queries x 1 kv-head per block, 160 threads, K direct to regs
// (no K smem) -> ~45.6KB smem, 3 blocks/SM (reg-limited).
// ---------------------------------------------------------------------------
#define KV_PITCH 66
#define VS_FLOATS 8648    // 131*66 = 8646, padded to multiple of 4
#define ATTN_SMEM ((VS_FLOATS + 2048 + 4 * 160 + 64) * 4)

__global__ __launch_bounds__(160, 3) void attn_kernel(
    const float* __restrict__ qkv, const float* __restrict__ sinks,
    __half* __restrict__ cpk)
{
    extern __shared__ float sm[];
    float* vs   = sm;                          // 131*66 (padded to 8648)
    float* qsm  = vs + VS_FLOATS;              // 2048, 16B-aligned
    float* sc   = qsm + 2048;                  // 4*160
    float* redm = sc + 4 * 160;                // 32
    float* reds = redm + 32;                   // 32

    const int q0  = blockIdx.x * 4;
    const int kh  = blockIdx.y;
    const int b   = blockIdx.z;
    const int tid = threadIdx.x;
    const int lane = tid & 31, w = tid >> 5;
    const int kstartU = (q0 >= 127) ? q0 - 127 : 0;
    const int cntU = q0 + 3 - kstartU + 1;

    for (int i = tid; i < 2048; i += 160) {
        int qq = i >> 9, r = i & 511;
        qsm[r * 4 + qq] = qkv[(size_t)(b * S_LEN + q0 + qq) * QKV_COLS + kh * 512 + r];
    }
    for (int i = tid; i < cntU * 64; i += 160) {
        int r = i >> 6, d = i & 63;
        size_t rb = (size_t)(b * S_LEN + kstartU + r) * QKV_COLS;
        vs[r * KV_PITCH + d] = qkv[rb + 4608 + kh * 64 + d];
    }

    const bool havek = tid < cntU;
    float kreg[64];
    if (havek) {
        const float4* kp = (const float4*)(qkv +
            (size_t)(b * S_LEN + kstartU + tid) * QKV_COLS + 4096 + kh * 64);
#pragma unroll
        for (int u = 0; u < 16; u++) {
            float4 v = kp[u];
            kreg[u * 4 + 0] = v.x; kreg[u * 4 + 1] = v.y;
            kreg[u * 4 + 2] = v.z; kreg[u * 4 + 3] = v.w;
        }
    } else {
#pragma unroll
        for (int d = 0; d < 64; d++) kreg[d] = 0.0f;
    }
    __syncthreads();

    const int kpos = kstartU + tid;

    for (int h8 = 0; h8 < 8; h8++) {
        const float sink = sinks[kh * 8 + h8];
        float s[4] = {-1e30f, -1e30f, -1e30f, -1e30f};
        if (havek) {
            float a0 = 0.f, a1 = 0.f, a2 = 0.f, a3 = 0.f;
            const float4* qp = (const float4*)(qsm + h8 * 256);
#pragma unroll
            for (int d = 0; d < 64; d++) {
                float4 qv = qp[d];
                float kd = kreg[d];
                a0 = fmaf(kd, qv.x, a0);
                a1 = fmaf(kd, qv.y, a1);
                a2 = fmaf(kd, qv.z, a2);
                a3 = fmaf(kd, qv.w, a3);
            }
            float aa[4] = {a0, a1, a2, a3};
#pragma unroll
            for (int qq = 0; qq < 4; qq++) {
                int qg = q0 + qq;
                int loG = qg - 127; if (loG < 0) loG = 0;
                s[qq] = (kpos >= loG && kpos <= qg) ? aa[qq] * 0.125f : -1e30f;
            }
        }
#pragma unroll
        for (int qq = 0; qq < 4; qq++) {
            float m = s[qq];
#pragma unroll
            for (int o = 16; o; o >>= 1) m = fmaxf(m, __shfl_xor_sync(0xffffffffu, m, o));
            if (lane == 0) redm[qq * 8 + w] = m;
        }
        __syncthreads();
        float mq[4], denomq[4];
#pragma unroll
        for (int qq = 0; qq < 4; qq++) {
            float m = redm[qq * 8];
#pragma unroll
            for (int j = 1; j < 5; j++) m = fmaxf(m, redm[qq * 8 + j]);
            mq[qq] = fmaxf(m, sink);
        }
#pragma unroll
        for (int qq = 0; qq < 4; qq++) {
            float p = fexp(s[qq] - mq[qq]);
            sc[qq * 160 + tid] = p;
#pragma unroll
            for (int o = 16; o; o >>= 1) p += __shfl_xor_sync(0xffffffffu, p, o);
            if (lane == 0) reds[qq * 8 + w] = p;
        }
        __syncthreads();
#pragma unroll
        for (int qq = 0; qq < 4; qq++) {
            float sum = reds[qq * 8] + reds[qq * 8 + 1] + reds[qq * 8 + 2] +
                        reds[qq * 8 + 3] + reds[qq * 8 + 4];
            denomq[qq] = sum + fexp(sink - mq[qq]);
        }
        if (w < 4) {
            const int qg = q0 + w;
            int loG = qg - 127; if (loG < 0) loG = 0;
            const int lo = loG - kstartU, hi = qg - kstartU;
            float2 acc = {0.f, 0.f};
            const float* scw = sc + w * 160;
            const float* vb = vs + lane * 2;
            for (int j = lo; j <= hi; j++) {
                float p = scw[j];
                float2 v = *(const float2*)(vb + j * KV_PITCH);
                acc.x = fmaf(p, v.x, acc.x);
                acc.y = fmaf(p, v.y, acc.y);
            }
            float inv = 1.0f / denomq[w];
            int t = b * S_LEN + qg;
            int kcol = (kh * 8 + h8) * 64 + lane * 2;
            size_t o = offP(t, kcol, NKC_O);
            *(__half2*)(cpk + o) = __floats2half2_rn(acc.x * inv, acc.y * inv);
        }
        __syncthreads();
    }
}

// ---------------------------------------------------------------------------
// Launch
// ---------------------------------------------------------------------------
extern "C" void kernel_launch(void* const* d_in, const int* in_sizes, int n_in,
                              void* d_out, int out_size) {
    const float* x     = (const float*)d_in[0];
    const float* wq    = (const float*)d_in[1];
    const float* bq    = (const float*)d_in[2];
    const float* wk    = (const float*)d_in[3];
    const float* bk    = (const float*)d_in[4];
    const float* wv    = (const float*)d_in[5];
    const float* bv    = (const float*)d_in[6];
    const float* wo    = (const float*)d_in[7];
    const float* bo    = (const float*)d_in[8];
    const float* sinks = (const float*)d_in[9];
    const int* positions = (const int*)d_in[10];
    float* out = (float*)d_out;

    void *xpk, *wbh, *wobh, *cpk, *qkv, *qkvp_part, *opart, *biasqkv;
    cudaGetSymbolAddress(&xpk, g_xpk);
    cudaGetSymbolAddress(&wbh, g_wbh);
    cudaGetSymbolAddress(&wobh, g_wobh);
    cudaGetSymbolAddress(&cpk, g_cpk);
    cudaGetSymbolAddress(&qkv, g_qkv);
    cudaGetSymbolAddress(&qkvp_part, g_qkvp);
    cudaGetSymbolAddress(&opart, g_opart);
    cudaGetSymbolAddress(&biasqkv, g_biasqkv);

    float* qkvp = (float*)qkv;
    float* qkvpartp = (float*)qkvp_part;
    float* opartp = (float*)opart;

    cudaFuncSetAttribute(gemm_tc, cudaFuncAttributeMaxDynamicSharedMemorySize, GEMM_SMEM);
    cudaFuncSetAttribute(attn_kernel, cudaFuncAttributeMaxDynamicSharedMemorySize, ATTN_SMEM);

    // 1. pack inputs/weights (single fp16 plane each, 512B-contiguous stores)
    pack_x<<<dim3((T_TOK / 8) * NKC_QKV * 32 / 256, 1), 256>>>(x, (__half*)xpk);
    tsp1<<<dim3(NH / 64, D_DIM / 64), dim3(32, 8)>>>(wq, (__half*)wbh, D_DIM, NH, NKC_QKV, 0);
    tsp1<<<dim3(KVH / 64, D_DIM / 64), dim3(32, 8)>>>(wk, (__half*)wbh, D_DIM, KVH, NKC_QKV, NH);
    tsp1<<<dim3(KVH / 64, D_DIM / 64), dim3(32, 8)>>>(wv, (__half*)wbh, D_DIM, KVH, NKC_QKV, NH + KVH);
    tsp1<<<dim3(OPAD / 64, NH / 64), dim3(32, 8)>>>(wo, (__half*)wobh, NH, D_DIM, NKC_O, 0);
    concat_bias<<<(QKV_COLS + 255) / 256, 256>>>(bq, bk, bv, (float*)biasqkv);

    // 2. QKV projection: split-K=2 in one launch (z), then fused combine+rope
    gemm_tc<<<dim3(QKV_COLS / 128, T_TOK / 128, 2), 256, GEMM_SMEM>>>(
        (const __half*)xpk, (const __half*)wbh, qkvpartp,
        NKC_QKV, NKC_QKV / 2, QKV_COLS, QKV_COLS, (size_t)T_TOK * QKV_COLS);
    combine_qkv_rope<<<T_TOK, 256>>>(qkvpartp, (const float*)biasqkv, positions, qkvp);

    // 3. attention (writes packed fp16 ctx)
    attn_kernel<<<dim3(S_LEN / 4, 8, B_BATCH), 160, ATTN_SMEM>>>(
        qkvp, sinks, (__half*)cpk);

    // 4. output projection: split-K=2 in one launch (z), then combine (+bias)
    gemm_tc<<<dim3(OPAD / 128, T_TOK / 128, 2), 256, GEMM_SMEM>>>(
        (const __half*)cpk, (const __half*)wobh, opartp,
        NKC_O, NKC_O / 2, OPAD, OPAD, (size_t)T_TOK * OPAD);
    combine_o<<<T_TOK, 256>>>(opartp, bo, out);
}

// round 13
// speedup vs baseline: 1.0841x; 1.0423x over previous
#include <cuda_runtime.h>
#include <cuda_fp16.h>
#include <cstdint>

// ---------------------------------------------------------------------------
// Problem constants
// ---------------------------------------------------------------------------
#define T_TOK   2048
#define D_DIM   2880
#define S_LEN   1024
#define B_BATCH 2
#define WIN     128
#define NH      4096
#define KVH     512
#define QKV_COLS 5120
#define OPAD    2944
#define NKC_QKV 90        // 2880/32
#define NKC_O   128       // 4096/32

// ---------------------------------------------------------------------------
// Scratch
// ---------------------------------------------------------------------------
__device__ __half g_xpk [(size_t)16 * NKC_QKV * 128 * 32];   // x packed fp16 (A blobs)
__device__ __half g_wbh [(size_t)40 * NKC_QKV * 128 * 32];   // qkv weights (B blobs)
__device__ __half g_wobh[(size_t)23 * NKC_O   * 128 * 32];   // wo (B blobs)
__device__ __half g_cpk [(size_t)16 * NKC_O   * 128 * 32];   // ctx packed fp16 (A blobs)
__device__ float  g_qkv  [(size_t)T_TOK * QKV_COLS];
__device__ float  g_qkvp [(size_t)2 * T_TOK * QKV_COLS];     // QKV split-K partials
__device__ float  g_opart[(size_t)2 * T_TOK * OPAD];         // O split-K partials
__device__ float  g_biasqkv[QKV_COLS];

// ---------------------------------------------------------------------------
// Packed layout: 128-row x 32-k tiles, row = 64B, 16B chunks XOR-swizzled by
// ((row>>1)&3) so ldmatrix is conflict-free while bulk copies stay linear.
// ---------------------------------------------------------------------------
__device__ __forceinline__ size_t offP(int r_glob, int k, int nkc) {
    int r = r_glob & 127, ck = (k >> 3) & 3, w = k & 7;
    return ((((size_t)(r_glob >> 7)) * nkc + (k >> 5)) * 128 + r) * 32 +
           (((ck ^ ((r >> 1) & 3)) << 3) + w);
}

// ---------------------------------------------------------------------------
// PTX helpers
// ---------------------------------------------------------------------------
__device__ __forceinline__ void mbar_init(uint32_t a, uint32_t cnt) {
    asm volatile("mbarrier.init.shared.b64 [%0], %1;" :: "r"(a), "r"(cnt) : "memory");
}
__device__ __forceinline__ void mbar_wait(uint32_t a, int ph) {
    uint32_t done = 0;
    while (!done) {
        asm volatile("{\n\t.reg .pred p;\n\t"
                     "mbarrier.try_wait.parity.acquire.cta.shared::cta.b64 p, [%1], %2, 0x989680;\n\t"
                     "selp.b32 %0,1,0,p;\n\t}"
                     : "=r"(done) : "r"(a), "r"((uint32_t)ph) : "memory");
    }
}
__device__ __forceinline__ void expect_tx(uint32_t a, uint32_t bytes) {
    asm volatile("mbarrier.arrive.expect_tx.shared::cta.b64 _, [%0], %1;"
                 :: "r"(a), "r"(bytes) : "memory");
}
__device__ __forceinline__ void bulk_g2s(uint32_t sdst, const void* gsrc,
                                         uint32_t bytes, uint32_t mbar) {
    asm volatile("cp.async.bulk.shared::cluster.global.mbarrier::complete_tx::bytes "
                 "[%0], [%1], %2, [%3];"
                 :: "r"(sdst), "l"(__cvta_generic_to_global(gsrc)), "r"(bytes), "r"(mbar)
                 : "memory");
}
__device__ __forceinline__ void ldmx4(uint32_t* d, uint32_t addr) {
    asm volatile("ldmatrix.sync.aligned.m8n8.x4.shared.b16 {%0,%1,%2,%3}, [%4];"
                 : "=r"(d[0]), "=r"(d[1]), "=r"(d[2]), "=r"(d[3]) : "r"(addr));
}
__device__ __forceinline__ void mma16816(float* c, const uint32_t* a, const uint32_t* b) {
    asm volatile(
        "mma.sync.aligned.m16n8k16.row.col.f32.f16.f16.f32 "
        "{%0,%1,%2,%3},{%4,%5,%6,%7},{%8,%9},{%0,%1,%2,%3};\n"
        : "+f"(c[0]), "+f"(c[1]), "+f"(c[2]), "+f"(c[3])
        : "r"(a[0]), "r"(a[1]), "r"(a[2]), "r"(a[3]), "r"(b[0]), "r"(b[1]));
}

// fast exp on the FMA pipe (x <= 0 path), rel err ~1e-7
__device__ __forceinline__ float fexp(float x) {
    x = fmaxf(x, -87.0f);
    float y = x * 1.44269504f;
    float n = rintf(y);
    float f = y - n;
    float p = 1.33336498e-3f;
    p = fmaf(p, f, 9.61011233e-3f);
    p = fmaf(p, f, 5.55040755e-2f);
    p = fmaf(p, f, 2.40226507e-1f);
    p = fmaf(p, f, 6.93147182e-1f);
    p = fmaf(p, f, 1.0f);
    return p * __int_as_float(((int)n + 127) << 23);
}

// ---------------------------------------------------------------------------
// Fused prep: one launch does all weight transposes + x pack + bias concat.
// Block-range dispatch over 9444 blocks.
// ---------------------------------------------------------------------------
__device__ void dev_tsp(const float* __restrict__ in, __half* __restrict__ oh,
                        float (*tb)[65], int C, int nkc, int nbase,
                        int bx, int by, int tid) {
    int c0 = bx * 64, r0 = by * 64;
    int tx = tid & 31, ty = tid >> 5;
#pragma unroll
    for (int i = 0; i < 8; i++) {
        int r = r0 + ty + i * 8;
#pragma unroll
        for (int cc = 0; cc < 2; cc++) {
            int c = c0 + cc * 32 + tx;
            tb[ty + i * 8][cc * 32 + tx] = (c < C) ? in[(size_t)r * C + c] : 0.0f;
        }
    }
    __syncthreads();
    int nrow = tid >> 2;
    int ckg = tid & 3;
    int n = nbase + c0 + nrow;
#pragma unroll
    for (int half = 0; half < 2; half++) {
        int ck = ckg + half * 4;
        int k = r0 + ck * 8;
        __half h[8];
#pragma unroll
        for (int w = 0; w < 8; w++)
            h[w] = __float2half_rn(tb[ck * 8 + w][nrow]);
        *(uint4*)(oh + offP(n, k, nkc)) = *(const uint4*)h;
    }
}

__device__ void dev_pack_x(const float* __restrict__ x, __half* __restrict__ o,
                           int blk, int tid) {
    int gw = blk * 8 + (tid >> 5);
    int lane = tid & 31;
    int kt = gw % NKC_QKV;
    int tb = gw / NKC_QKV;
    if (tb >= T_TOK / 8) return;
    int j = lane >> 2, c = lane & 3;
    int t = tb * 8 + j;
    int k = kt * 32 + c * 8;
    const float* src = x + (size_t)t * D_DIM + k;
    float4 v0 = *(const float4*)src;
    float4 v1 = *(const float4*)(src + 4);
    __half h[8];
    h[0] = __float2half_rn(v0.x); h[1] = __float2half_rn(v0.y);
    h[2] = __float2half_rn(v0.z); h[3] = __float2half_rn(v0.w);
    h[4] = __float2half_rn(v1.x); h[5] = __float2half_rn(v1.y);
    h[6] = __float2half_rn(v1.z); h[7] = __float2half_rn(v1.w);
    *(uint4*)(o + offP(t, k, NKC_QKV)) = *(const uint4*)h;
}

#define PREP_WQ_END   2880     // 64 x 45
#define PREP_WK_END   3240     // + 8 x 45
#define PREP_WV_END   3600     // + 8 x 45
#define PREP_WO_END   6544     // + 46 x 64
#define PREP_X_END    9424     // + 2880
#define PREP_TOTAL    9444     // + 20 bias

__global__ __launch_bounds__(256) void prep_all(
    const float* __restrict__ x,  const float* __restrict__ wq,
    const float* __restrict__ wk, const float* __restrict__ wv,
    const float* __restrict__ wo, const float* __restrict__ bq,
    const float* __restrict__ bk, const float* __restrict__ bv,
    __half* __restrict__ xpk, __half* __restrict__ wbh,
    __half* __restrict__ wobh, float* __restrict__ biasqkv)
{
    __shared__ float tb[64][65];
    int blk = blockIdx.x;
    int tid = threadIdx.x;
    if (blk < PREP_WQ_END) {
        dev_tsp(wq, wbh, tb, NH, NKC_QKV, 0, blk % 64, blk / 64, tid);
    } else if (blk < PREP_WK_END) {
        blk -= PREP_WQ_END;
        dev_tsp(wk, wbh, tb, KVH, NKC_QKV, NH, blk % 8, blk / 8, tid);
    } else if (blk < PREP_WV_END) {
        blk -= PREP_WK_END;
        dev_tsp(wv, wbh, tb, KVH, NKC_QKV, NH + KVH, blk % 8, blk / 8, tid);
    } else if (blk < PREP_WO_END) {
        blk -= PREP_WV_END;
        dev_tsp(wo, wobh, tb, D_DIM, NKC_O, 0, blk % 46, blk / 46, tid);
    } else if (blk < PREP_X_END) {
        dev_pack_x(x, xpk, blk - PREP_WO_END, tid);
    } else {
        int i = (blk - PREP_X_END) * 256 + tid;
        if (i < QKV_COLS)
            biasqkv[i] = (i < NH) ? bq[i] : (i < NH + KVH ? bk[i - NH] : bv[i - NH - KVH]);
    }
}

// ---------------------------------------------------------------------------
// Fused: combine QKV split-K partials + bias + RoPE -> qkv buffer
// ---------------------------------------------------------------------------
__global__ __launch_bounds__(256) void combine_qkv_rope(
    const float* __restrict__ part, const float* __restrict__ bias,
    const int* __restrict__ positions, float* __restrict__ qkv)
{
    __shared__ float row[NH + KVH];
    __shared__ float cs[32], sn[32];
    const int t = blockIdx.x;
    const int tid = threadIdx.x;

    if (tid < 32) {
        int i = tid;
        int pos = positions[t] % S_LEN;
        float freq   = powf(150000.0f, (float)i / 32.0f);
        float interp = 1.0f / (32.0f * freq);
        float extrap = 1.0f / freq;
        float lnT    = logf(150000.0f);
        float low    = 32.0f * logf(4096.0f / (32.0f * 6.2831853071795864f)) / lnT;
        float high   = 32.0f * logf(4096.0f / 6.2831853071795864f) / lnT;
        float ramp   = fminf(fmaxf(((float)i - low) / (high - low), 0.0f), 1.0f);
        float inv    = interp * ramp + extrap * (1.0f - ramp);
        float conc   = 0.1f * logf(32.0f) + 1.0f;
        float tt     = (float)pos * inv;
        cs[i] = cosf(tt) * conc;
        sn[i] = sinf(tt) * conc;
    }

    const float* p0 = part + (size_t)t * QKV_COLS;
    const float* p1 = part + (size_t)T_TOK * QKV_COLS + (size_t)t * QKV_COLS;
    float* orow = qkv + (size_t)t * QKV_COLS;

    for (int c = tid * 4; c < QKV_COLS; c += 256 * 4) {
        float4 a = *(const float4*)(p0 + c);
        float4 b = *(const float4*)(p1 + c);
        float4 bb = *(const float4*)(bias + c);
        float4 r;
        r.x = a.x + b.x + bb.x;
        r.y = a.y + b.y + bb.y;
        r.z = a.z + b.z + bb.z;
        r.w = a.w + b.w + bb.w;
        if (c >= NH + KVH) {            // V columns: no rope, write directly
            *(float4*)(orow + c) = r;
        } else {
            *(float4*)(row + c) = r;
        }
    }
    __syncthreads();

    for (int idx = tid; idx < 72 * 32; idx += 256) {
        int head = idx >> 5, i = idx & 31;
        float x1 = row[head * 64 + i], x2 = row[head * 64 + i + 32];
        orow[head * 64 + i]      = x1 * cs[i] - x2 * sn[i];
        orow[head * 64 + i + 32] = x2 * cs[i] + x1 * sn[i];
    }
}

// combine O split-K partials + bias -> final output [T, 2880]
__global__ void combine_o(const float* __restrict__ part, const float* __restrict__ bo,
                          float* __restrict__ out) {
    const int t = blockIdx.x;
    const float* p0 = part + (size_t)t * OPAD;
    const float* p1 = part + (size_t)T_TOK * OPAD + (size_t)t * OPAD;
    float* o = out + (size_t)t * D_DIM;
    for (int c = threadIdx.x * 4; c < D_DIM; c += 256 * 4) {
        float4 a = *(const float4*)(p0 + c);
        float4 b = *(const float4*)(p1 + c);
        float4 bb = *(const float4*)(bo + c);
        float4 r;
        r.x = a.x + b.x + bb.x;
        r.y = a.y + b.y + bb.y;
        r.z = a.z + b.z + bb.z;
        r.w = a.w + b.w + bb.w;
        *(float4*)(o + c) = r;
    }
}

// ---------------------------------------------------------------------------
// GEMM: 128x128 CTA tile, 256 threads (8 warps of 64x32), 2 CTAs/SM,
// 4-stage cp.async.bulk pipeline; full 4-stage upfront fill, then sync +
// dual-chunk prefetch every SECOND iteration (halves barrier count).
// grid.z = split-K slice: kbase = z*nkc_run, C += z*plane_stride.
// ---------------------------------------------------------------------------
#define STAGE_BYTES 16384
#define NSTAGE      4
#define GEMM_SMEM   (128 + NSTAGE * STAGE_BYTES)

__global__ __launch_bounds__(256, 2) void gemm_tc(
    const __half* __restrict__ Apk, const __half* __restrict__ Bhp,
    float* __restrict__ C,
    int nkc_total, int nkc_run, int Nreal, int ldc, size_t plane_stride)
{
    extern __shared__ __align__(128) uint8_t dsm[];
    const uint32_t base = (uint32_t)__cvta_generic_to_shared(dsm);
    const uint32_t mb = base;
    const uint32_t sdata = base + 128;

    const int tid = threadIdx.x, lane = tid & 31, warp = tid >> 5;
    const int wm = warp >> 2, wn = warp & 3;
    const int mt = blockIdx.y, nt = blockIdx.x;
    const int kbase = blockIdx.z * nkc_run;
    C += (size_t)blockIdx.z * plane_stride;

    if (tid == 0)
#pragma unroll
        for (int s = 0; s < NSTAGE; s++) mbar_init(mb + s * 8, 1);
    __syncthreads();

    const __half* Asrc = Apk + (size_t)mt * nkc_total * 4096 + (size_t)kbase * 4096;
    const __half* Bsrc = Bhp + (size_t)nt * nkc_total * 4096 + (size_t)kbase * 4096;

    float c[4][4][4];
#pragma unroll
    for (int mi = 0; mi < 4; mi++)
#pragma unroll
        for (int ni = 0; ni < 4; ni++)
#pragma unroll
            for (int r = 0; r < 4; r++) c[mi][ni][r] = 0.0f;

    if (tid == 0) {
#pragma unroll
        for (int s = 0; s < NSTAGE; s++) {
            if (s < nkc_run) {
                uint32_t sb = sdata + s * STAGE_BYTES;
                expect_tx(mb + s * 8, 16384u);
                bulk_g2s(sb,        Asrc + (size_t)s * 4096, 8192, mb + s * 8);
                bulk_g2s(sb + 8192, Bsrc + (size_t)s * 4096, 8192, mb + s * 8);
            }
        }
    }

    const int rA_l = lane & 15;
    const int ckA_l = lane >> 4;
    const int rB_l = (lane & 7) + ((lane >> 4) << 3);
    const int ckB_l = (lane >> 3) & 1;

    for (int i = 0; i < nkc_run; i++) {
        const int s = i & (NSTAGE - 1);
        const int ph = (i >> 2) & 1;
        mbar_wait(mb + s * 8, ph);

        const uint32_t sA = sdata + s * STAGE_BYTES;
        const uint32_t sB = sA + 8192;

#pragma unroll
        for (int ks = 0; ks < 2; ks++) {
            uint32_t a[4][4];
#pragma unroll
            for (int mi = 0; mi < 4; mi++) {
                int r = wm * 64 + mi * 16 + rA_l;
                int ck = ks * 2 + ckA_l;
                ldmx4(a[mi], sA + r * 64 + ((ck ^ ((r >> 1) & 3)) << 4));
            }
            uint32_t b[4][2];
            {
                int ck = ks * 2 + ckB_l;
#pragma unroll
                for (int p = 0; p < 2; p++) {
                    int r = wn * 32 + p * 16 + rB_l;
                    uint32_t d[4];
                    ldmx4(d, sB + r * 64 + ((ck ^ ((r >> 1) & 3)) << 4));
                    b[p * 2][0] = d[0]; b[p * 2][1] = d[1];
                    b[p * 2 + 1][0] = d[2]; b[p * 2 + 1][1] = d[3];
                }
            }
#pragma unroll
            for (int mi = 0; mi < 4; mi++)
#pragma unroll
                for (int ni = 0; ni < 4; ni++) mma16816(c[mi][ni], a[mi], b[ni]);
        }
        // sync + dual prefetch only after odd iterations (covers i-1 and i)
        if ((i & 1) && i + 3 < nkc_run + 2) {
            __syncthreads();
            if (tid == 0) {
#pragma unroll
                for (int q = 3; q <= 4; q++) {
                    int j = i + q;
                    if (j < nkc_run) {
                        const int s2 = j & (NSTAGE - 1);
                        uint32_t sb = sdata + s2 * STAGE_BYTES;
                        expect_tx(mb + s2 * 8, 16384u);
                        bulk_g2s(sb,        Asrc + (size_t)j * 4096, 8192, mb + s2 * 8);
                        bulk_g2s(sb + 8192, Bsrc + (size_t)j * 4096, 8192, mb + s2 * 8);
                    }
                }
            }
        }
    }

#pragma unroll
    for (int mi = 0; mi < 4; mi++) {
        int row = mt * 128 + wm * 64 + mi * 16 + (lane >> 2);
#pragma unroll
        for (int ni = 0; ni < 4; ni++) {
            int col = nt * 128 + wn * 32 + ni * 8 + (lane & 3) * 2;
            if (col < Nreal) {
                float2 v0 = {c[mi][ni][0], c[mi][ni][1]};
                float2 v1 = {c[mi][ni][2], c[mi][ni][3]};
                *(float2*)(C + (size_t)row * ldc + col) = v0;
                *(float2*)(C + (size_t)(row + 8) * ldc + col) = v1;
            }
        }
    }
}

// ---------------------------------------------------------------------------
// Attention: 4 queries x 1 kv-head per block, 160 threads, K direct to regs
// (no K smem) -> ~45.6KB smem, 3 blocks/SM (reg-limited).
// ---------------------------------------------------------------------------
#define KV_PITCH 66
#define VS_FLOATS 8648    // 131*66 = 8646, padded to multiple of 4
#define ATTN_SMEM ((VS_FLOATS + 2048 + 4 * 160 + 64) * 4)

__global__ __launch_bounds__(160, 3) void attn_kernel(
    const float* __restrict__ qkv, const float* __restrict__ sinks,
    __half* __restrict__ cpk)
{
    extern __shared__ float sm[];
    float* vs   = sm;                          // 131*66 (padded to 8648)
    float* qsm  = vs + VS_FLOATS;              // 2048, 16B-aligned
    float* sc   = qsm + 2048;                  // 4*160
    float* redm = sc + 4 * 160;                // 32
    float* reds = redm + 32;                   // 32

    const int q0  = blockIdx.x * 4;
    const int kh  = blockIdx.y;
    const int b   = blockIdx.z;
    const int tid = threadIdx.x;
    const int lane = tid & 31, w = tid >> 5;
    const int kstartU = (q0 >= 127) ? q0 - 127 : 0;
    const int cntU = q0 + 3 - kstartU + 1;

    for (int i = tid; i < 2048; i += 160) {
        int qq = i >> 9, r = i & 511;
        qsm[r * 4 + qq] = qkv[(size_t)(b * S_LEN + q0 + qq) * QKV_COLS + kh * 512 + r];
    }
    for (int i = tid; i < cntU * 64; i += 160) {
        int r = i >> 6, d = i & 63;
        size_t rb = (size_t)(b * S_LEN + kstartU + r) * QKV_COLS;
        vs[r * KV_PITCH + d] = qkv[rb + 4608 + kh * 64 + d];
    }

    const bool havek = tid < cntU;
    float kreg[64];
    if (havek) {
        const float4* kp = (const float4*)(qkv +
            (size_t)(b * S_LEN + kstartU + tid) * QKV_COLS + 4096 + kh * 64);
#pragma unroll
        for (int u = 0; u < 16; u++) {
            float4 v = kp[u];
            kreg[u * 4 + 0] = v.x; kreg[u * 4 + 1] = v.y;
            kreg[u * 4 + 2] = v.z; kreg[u * 4 + 3] = v.w;
        }
    } else {
#pragma unroll
        for (int d = 0; d < 64; d++) kreg[d] = 0.0f;
    }
    __syncthreads();

    const int kpos = kstartU + tid;

    for (int h8 = 0; h8 < 8; h8++) {
        const float sink = sinks[kh * 8 + h8];
        float s[4] = {-1e30f, -1e30f, -1e30f, -1e30f};
        if (havek) {
            float a0 = 0.f, a1 = 0.f, a2 = 0.f, a3 = 0.f;
            const float4* qp = (const float4*)(qsm + h8 * 256);
#pragma unroll
            for (int d = 0; d < 64; d++) {
                float4 qv = qp[d];
                float kd = kreg[d];
                a0 = fmaf(kd, qv.x, a0);
                a1 = fmaf(kd, qv.y, a1);
                a2 = fmaf(kd, qv.z, a2);
                a3 = fmaf(kd, qv.w, a3);
            }
            float aa[4] = {a0, a1, a2, a3};
#pragma unroll
            for (int qq = 0; qq < 4; qq++) {
                int qg = q0 + qq;
                int loG = qg - 127; if (loG < 0) loG = 0;
                s[qq] = (kpos >= loG && kpos <= qg) ? aa[qq] * 0.125f : -1e30f;
            }
        }
#pragma unroll
        for (int qq = 0; qq < 4; qq++) {
            float m = s[qq];
#pragma unroll
            for (int o = 16; o; o >>= 1) m = fmaxf(m, __shfl_xor_sync(0xffffffffu, m, o));
            if (lane == 0) redm[qq * 8 + w] = m;
        }
        __syncthreads();
        float mq[4], denomq[4];
#pragma unroll
        for (int qq = 0; qq < 4; qq++) {
            float m = redm[qq * 8];
#pragma unroll
            for (int j = 1; j < 5; j++) m = fmaxf(m, redm[qq * 8 + j]);
            mq[qq] = fmaxf(m, sink);
        }
#pragma unroll
        for (int qq = 0; qq < 4; qq++) {
            float p = fexp(s[qq] - mq[qq]);
            sc[qq * 160 + tid] = p;
#pragma unroll
            for (int o = 16; o; o >>= 1) p += __shfl_xor_sync(0xffffffffu, p, o);
            if (lane == 0) reds[qq * 8 + w] = p;
        }
        __syncthreads();
#pragma unroll
        for (int qq = 0; qq < 4; qq++) {
            float sum = reds[qq * 8] + reds[qq * 8 + 1] + reds[qq * 8 + 2] +
                        reds[qq * 8 + 3] + reds[qq * 8 + 4];
            denomq[qq] = sum + fexp(sink - mq[qq]);
        }
        if (w < 4) {
            const int qg = q0 + w;
            int loG = qg - 127; if (loG < 0) loG = 0;
            const int lo = loG - kstartU, hi = qg - kstartU;
            float2 acc = {0.f, 0.f};
            const float* scw = sc + w * 160;
            const float* vb = vs + lane * 2;
            for (int j = lo; j <= hi; j++) {
                float p = scw[j];
                float2 v = *(const float2*)(vb + j * KV_PITCH);
                acc.x = fmaf(p, v.x, acc.x);
                acc.y = fmaf(p, v.y, acc.y);
            }
            float inv = 1.0f / denomq[w];
            int t = b * S_LEN + qg;
            int kcol = (kh * 8 + h8) * 64 + lane * 2;
            size_t o = offP(t, kcol, NKC_O);
            *(__half2*)(cpk + o) = __floats2half2_rn(acc.x * inv, acc.y * inv);
        }
        __syncthreads();
    }
}

// ---------------------------------------------------------------------------
// Launch
// ---------------------------------------------------------------------------
extern "C" void kernel_launch(void* const* d_in, const int* in_sizes, int n_in,
                              void* d_out, int out_size) {
    const float* x     = (const float*)d_in[0];
    const float* wq    = (const float*)d_in[1];
    const float* bq    = (const float*)d_in[2];
    const float* wk    = (const float*)d_in[3];
    const float* bk    = (const float*)d_in[4];
    const float* wv    = (const float*)d_in[5];
    const float* bv    = (const float*)d_in[6];
    const float* wo    = (const float*)d_in[7];
    const float* bo    = (const float*)d_in[8];
    const float* sinks = (const float*)d_in[9];
    const int* positions = (const int*)d_in[10];
    float* out = (float*)d_out;

    void *xpk, *wbh, *wobh, *cpk, *qkv, *qkvp_part, *opart, *biasqkv;
    cudaGetSymbolAddress(&xpk, g_xpk);
    cudaGetSymbolAddress(&wbh, g_wbh);
    cudaGetSymbolAddress(&wobh, g_wobh);
    cudaGetSymbolAddress(&cpk, g_cpk);
    cudaGetSymbolAddress(&qkv, g_qkv);
    cudaGetSymbolAddress(&qkvp_part, g_qkvp);
    cudaGetSymbolAddress(&opart, g_opart);
    cudaGetSymbolAddress(&biasqkv, g_biasqkv);

    float* qkvp = (float*)qkv;
    float* qkvpartp = (float*)qkvp_part;
    float* opartp = (float*)opart;

    cudaFuncSetAttribute(gemm_tc, cudaFuncAttributeMaxDynamicSharedMemorySize, GEMM_SMEM);
    cudaFuncSetAttribute(attn_kernel, cudaFuncAttributeMaxDynamicSharedMemorySize, ATTN_SMEM);

    // 1. all prep in one launch
    prep_all<<<PREP_TOTAL, 256>>>(x, wq, wk, wv, wo, bq, bk, bv,
                                  (__half*)xpk, (__half*)wbh, (__half*)wobh,
                                  (float*)biasqkv);

    // 2. QKV projection: split-K=2 in one launch (z), then fused combine+rope
    gemm_tc<<<dim3(QKV_COLS / 128, T_TOK / 128, 2), 256, GEMM_SMEM>>>(
        (const __half*)xpk, (const __half*)wbh, qkvpartp,
        NKC_QKV, NKC_QKV / 2, QKV_COLS, QKV_COLS, (size_t)T_TOK * QKV_COLS);
    combine_qkv_rope<<<T_TOK, 256>>>(qkvpartp, (const float*)biasqkv, positions, qkvp);

    // 3. attention (writes packed fp16 ctx)
    attn_kernel<<<dim3(S_LEN / 4, 8, B_BATCH), 160, ATTN_SMEM>>>(
        qkvp, sinks, (__half*)cpk);

    // 4. output projection: split-K=2 in one launch (z), then combine (+bias)
    gemm_tc<<<dim3(OPAD / 128, T_TOK / 128, 2), 256, GEMM_SMEM>>>(
        (const __half*)cpk, (const __half*)wobh, opartp,
        NKC_O, NKC_O / 2, OPAD, OPAD, (size_t)T_TOK * OPAD);
    combine_o<<<T_TOK, 256>>>(opartp, bo, out);
}

// round 14
// speedup vs baseline: 1.1593x; 1.0694x over previous
#include <cuda_runtime.h>
#include <cuda_fp16.h>
#include <cstdint>

// ---------------------------------------------------------------------------
// Problem constants
// ---------------------------------------------------------------------------
#define T_TOK   2048
#define D_DIM   2880
#define S_LEN   1024
#define B_BATCH 2
#define WIN     128
#define NH      4096
#define KVH     512
#define QKV_COLS 5120
#define OPAD    2944
#define NKC_QKV 90        // 2880/32
#define NKC_O   128       // 4096/32

// ---------------------------------------------------------------------------
// Scratch
// ---------------------------------------------------------------------------
__device__ __half g_xpk [(size_t)16 * NKC_QKV * 128 * 32];   // x packed fp16 (A blobs)
__device__ __half g_wbh [(size_t)40 * NKC_QKV * 128 * 32];   // qkv weights (B blobs)
__device__ __half g_wobh[(size_t)23 * NKC_O   * 128 * 32];   // wo (B blobs)
__device__ __half g_cpk [(size_t)16 * NKC_O   * 128 * 32];   // ctx packed fp16 (A blobs)
__device__ float  g_qkv  [(size_t)T_TOK * QKV_COLS];
__device__ float  g_qkvp [(size_t)2 * T_TOK * QKV_COLS];     // QKV split-K partials
__device__ float  g_opart[(size_t)2 * T_TOK * OPAD];         // O split-K partials
__device__ float  g_biasqkv[QKV_COLS];

// ---------------------------------------------------------------------------
// Packed layout: 128-row x 32-k tiles, row = 64B, 16B chunks XOR-swizzled by
// ((row>>1)&3) so ldmatrix is conflict-free while bulk copies stay linear.
// ---------------------------------------------------------------------------
__device__ __forceinline__ size_t offP(int r_glob, int k, int nkc) {
    int r = r_glob & 127, ck = (k >> 3) & 3, w = k & 7;
    return ((((size_t)(r_glob >> 7)) * nkc + (k >> 5)) * 128 + r) * 32 +
           (((ck ^ ((r >> 1) & 3)) << 3) + w);
}

// ---------------------------------------------------------------------------
// PTX helpers
// ---------------------------------------------------------------------------
__device__ __forceinline__ void mbar_init(uint32_t a, uint32_t cnt) {
    asm volatile("mbarrier.init.shared.b64 [%0], %1;" :: "r"(a), "r"(cnt) : "memory");
}
__device__ __forceinline__ void mbar_wait(uint32_t a, int ph) {
    uint32_t done = 0;
    while (!done) {
        asm volatile("{\n\t.reg .pred p;\n\t"
                     "mbarrier.try_wait.parity.acquire.cta.shared::cta.b64 p, [%1], %2, 0x989680;\n\t"
                     "selp.b32 %0,1,0,p;\n\t}"
                     : "=r"(done) : "r"(a), "r"((uint32_t)ph) : "memory");
    }
}
__device__ __forceinline__ void expect_tx(uint32_t a, uint32_t bytes) {
    asm volatile("mbarrier.arrive.expect_tx.shared::cta.b64 _, [%0], %1;"
                 :: "r"(a), "r"(bytes) : "memory");
}
__device__ __forceinline__ void bulk_g2s(uint32_t sdst, const void* gsrc,
                                         uint32_t bytes, uint32_t mbar) {
    asm volatile("cp.async.bulk.shared::cluster.global.mbarrier::complete_tx::bytes "
                 "[%0], [%1], %2, [%3];"
                 :: "r"(sdst), "l"(__cvta_generic_to_global(gsrc)), "r"(bytes), "r"(mbar)
                 : "memory");
}
__device__ __forceinline__ void ldmx4(uint32_t* d, uint32_t addr) {
    asm volatile("ldmatrix.sync.aligned.m8n8.x4.shared.b16 {%0,%1,%2,%3}, [%4];"
                 : "=r"(d[0]), "=r"(d[1]), "=r"(d[2]), "=r"(d[3]) : "r"(addr));
}
__device__ __forceinline__ void mma16816(float* c, const uint32_t* a, const uint32_t* b) {
    asm volatile(
        "mma.sync.aligned.m16n8k16.row.col.f32.f16.f16.f32 "
        "{%0,%1,%2,%3},{%4,%5,%6,%7},{%8,%9},{%0,%1,%2,%3};\n"
        : "+f"(c[0]), "+f"(c[1]), "+f"(c[2]), "+f"(c[3])
        : "r"(a[0]), "r"(a[1]), "r"(a[2]), "r"(a[3]), "r"(b[0]), "r"(b[1]));
}

// fast exp on the FMA pipe (x <= 0 path), rel err ~1e-7
__device__ __forceinline__ float fexp(float x) {
    x = fmaxf(x, -87.0f);
    float y = x * 1.44269504f;
    float n = rintf(y);
    float f = y - n;
    float p = 1.33336498e-3f;
    p = fmaf(p, f, 9.61011233e-3f);
    p = fmaf(p, f, 5.55040755e-2f);
    p = fmaf(p, f, 2.40226507e-1f);
    p = fmaf(p, f, 6.93147182e-1f);
    p = fmaf(p, f, 1.0f);
    return p * __int_as_float(((int)n + 127) << 23);
}

// ---------------------------------------------------------------------------
// Fused prep: one launch does all weight transposes + x pack + bias concat.
// ---------------------------------------------------------------------------
__device__ void dev_tsp(const float* __restrict__ in, __half* __restrict__ oh,
                        float (*tb)[65], int C, int nkc, int nbase,
                        int bx, int by, int tid) {
    int c0 = bx * 64, r0 = by * 64;
    int tx = tid & 31, ty = tid >> 5;
#pragma unroll
    for (int i = 0; i < 8; i++) {
        int r = r0 + ty + i * 8;
#pragma unroll
        for (int cc = 0; cc < 2; cc++) {
            int c = c0 + cc * 32 + tx;
            tb[ty + i * 8][cc * 32 + tx] = (c < C) ? in[(size_t)r * C + c] : 0.0f;
        }
    }
    __syncthreads();
    int nrow = tid >> 2;
    int ckg = tid & 3;
    int n = nbase + c0 + nrow;
#pragma unroll
    for (int half = 0; half < 2; half++) {
        int ck = ckg + half * 4;
        int k = r0 + ck * 8;
        __half h[8];
#pragma unroll
        for (int w = 0; w < 8; w++)
            h[w] = __float2half_rn(tb[ck * 8 + w][nrow]);
        *(uint4*)(oh + offP(n, k, nkc)) = *(const uint4*)h;
    }
}

__device__ void dev_pack_x(const float* __restrict__ x, __half* __restrict__ o,
                           int blk, int tid) {
    int gw = blk * 8 + (tid >> 5);
    int lane = tid & 31;
    int kt = gw % NKC_QKV;
    int tb = gw / NKC_QKV;
    if (tb >= T_TOK / 8) return;
    int j = lane >> 2, c = lane & 3;
    int t = tb * 8 + j;
    int k = kt * 32 + c * 8;
    const float* src = x + (size_t)t * D_DIM + k;
    float4 v0 = *(const float4*)src;
    float4 v1 = *(const float4*)(src + 4);
    __half h[8];
    h[0] = __float2half_rn(v0.x); h[1] = __float2half_rn(v0.y);
    h[2] = __float2half_rn(v0.z); h[3] = __float2half_rn(v0.w);
    h[4] = __float2half_rn(v1.x); h[5] = __float2half_rn(v1.y);
    h[6] = __float2half_rn(v1.z); h[7] = __float2half_rn(v1.w);
    *(uint4*)(o + offP(t, k, NKC_QKV)) = *(const uint4*)h;
}

#define PREP_WQ_END   2880
#define PREP_WK_END   3240
#define PREP_WV_END   3600
#define PREP_WO_END   6544
#define PREP_X_END    9424
#define PREP_TOTAL    9444

__global__ __launch_bounds__(256) void prep_all(
    const float* __restrict__ x,  const float* __restrict__ wq,
    const float* __restrict__ wk, const float* __restrict__ wv,
    const float* __restrict__ wo, const float* __restrict__ bq,
    const float* __restrict__ bk, const float* __restrict__ bv,
    __half* __restrict__ xpk, __half* __restrict__ wbh,
    __half* __restrict__ wobh, float* __restrict__ biasqkv)
{
    __shared__ float tb[64][65];
    int blk = blockIdx.x;
    int tid = threadIdx.x;
    if (blk < PREP_WQ_END) {
        dev_tsp(wq, wbh, tb, NH, NKC_QKV, 0, blk % 64, blk / 64, tid);
    } else if (blk < PREP_WK_END) {
        blk -= PREP_WQ_END;
        dev_tsp(wk, wbh, tb, KVH, NKC_QKV, NH, blk % 8, blk / 8, tid);
    } else if (blk < PREP_WV_END) {
        blk -= PREP_WK_END;
        dev_tsp(wv, wbh, tb, KVH, NKC_QKV, NH + KVH, blk % 8, blk / 8, tid);
    } else if (blk < PREP_WO_END) {
        blk -= PREP_WV_END;
        dev_tsp(wo, wobh, tb, D_DIM, NKC_O, 0, blk % 46, blk / 46, tid);
    } else if (blk < PREP_X_END) {
        dev_pack_x(x, xpk, blk - PREP_WO_END, tid);
    } else {
        int i = (blk - PREP_X_END) * 256 + tid;
        if (i < QKV_COLS)
            biasqkv[i] = (i < NH) ? bq[i] : (i < NH + KVH ? bk[i - NH] : bv[i - NH - KVH]);
    }
}

// ---------------------------------------------------------------------------
// Fused: combine QKV split-K partials + bias + RoPE -> qkv buffer
// ---------------------------------------------------------------------------
__global__ __launch_bounds__(256) void combine_qkv_rope(
    const float* __restrict__ part, const float* __restrict__ bias,
    const int* __restrict__ positions, float* __restrict__ qkv)
{
    __shared__ float row[NH + KVH];
    __shared__ float cs[32], sn[32];
    const int t = blockIdx.x;
    const int tid = threadIdx.x;

    if (tid < 32) {
        int i = tid;
        int pos = positions[t] % S_LEN;
        float freq   = powf(150000.0f, (float)i / 32.0f);
        float interp = 1.0f / (32.0f * freq);
        float extrap = 1.0f / freq;
        float lnT    = logf(150000.0f);
        float low    = 32.0f * logf(4096.0f / (32.0f * 6.2831853071795864f)) / lnT;
        float high   = 32.0f * logf(4096.0f / 6.2831853071795864f) / lnT;
        float ramp   = fminf(fmaxf(((float)i - low) / (high - low), 0.0f), 1.0f);
        float inv    = interp * ramp + extrap * (1.0f - ramp);
        float conc   = 0.1f * logf(32.0f) + 1.0f;
        float tt     = (float)pos * inv;
        cs[i] = cosf(tt) * conc;
        sn[i] = sinf(tt) * conc;
    }

    const float* p0 = part + (size_t)t * QKV_COLS;
    const float* p1 = part + (size_t)T_TOK * QKV_COLS + (size_t)t * QKV_COLS;
    float* orow = qkv + (size_t)t * QKV_COLS;

    for (int c = tid * 4; c < QKV_COLS; c += 256 * 4) {
        float4 a = *(const float4*)(p0 + c);
        float4 b = *(const float4*)(p1 + c);
        float4 bb = *(const float4*)(bias + c);
        float4 r;
        r.x = a.x + b.x + bb.x;
        r.y = a.y + b.y + bb.y;
        r.z = a.z + b.z + bb.z;
        r.w = a.w + b.w + bb.w;
        if (c >= NH + KVH) {
            *(float4*)(orow + c) = r;
        } else {
            *(float4*)(row + c) = r;
        }
    }
    __syncthreads();

    for (int idx = tid; idx < 72 * 32; idx += 256) {
        int head = idx >> 5, i = idx & 31;
        float x1 = row[head * 64 + i], x2 = row[head * 64 + i + 32];
        orow[head * 64 + i]      = x1 * cs[i] - x2 * sn[i];
        orow[head * 64 + i + 32] = x2 * cs[i] + x1 * sn[i];
    }
}

// combine O split-K partials + bias -> final output [T, 2880]
__global__ void combine_o(const float* __restrict__ part, const float* __restrict__ bo,
                          float* __restrict__ out) {
    const int t = blockIdx.x;
    const float* p0 = part + (size_t)t * OPAD;
    const float* p1 = part + (size_t)T_TOK * OPAD + (size_t)t * OPAD;
    float* o = out + (size_t)t * D_DIM;
    for (int c = threadIdx.x * 4; c < D_DIM; c += 256 * 4) {
        float4 a = *(const float4*)(p0 + c);
        float4 b = *(const float4*)(p1 + c);
        float4 bb = *(const float4*)(bo + c);
        float4 r;
        r.x = a.x + b.x + bb.x;
        r.y = a.y + b.y + bb.y;
        r.z = a.z + b.z + bb.z;
        r.w = a.w + b.w + bb.w;
        *(float4*)(o + c) = r;
    }
}

// ---------------------------------------------------------------------------
// GEMM (unchanged from R13)
// ---------------------------------------------------------------------------
#define STAGE_BYTES 16384
#define NSTAGE      4
#define GEMM_SMEM   (128 + NSTAGE * STAGE_BYTES)

__global__ __launch_bounds__(256, 2) void gemm_tc(
    const __half* __restrict__ Apk, const __half* __restrict__ Bhp,
    float* __restrict__ C,
    int nkc_total, int nkc_run, int Nreal, int ldc, size_t plane_stride)
{
    extern __shared__ __align__(128) uint8_t dsm[];
    const uint32_t base = (uint32_t)__cvta_generic_to_shared(dsm);
    const uint32_t mb = base;
    const uint32_t sdata = base + 128;

    const int tid = threadIdx.x, lane = tid & 31, warp = tid >> 5;
    const int wm = warp >> 2, wn = warp & 3;
    const int mt = blockIdx.y, nt = blockIdx.x;
    const int kbase = blockIdx.z * nkc_run;
    C += (size_t)blockIdx.z * plane_stride;

    if (tid == 0)
#pragma unroll
        for (int s = 0; s < NSTAGE; s++) mbar_init(mb + s * 8, 1);
    __syncthreads();

    const __half* Asrc = Apk + (size_t)mt * nkc_total * 4096 + (size_t)kbase * 4096;
    const __half* Bsrc = Bhp + (size_t)nt * nkc_total * 4096 + (size_t)kbase * 4096;

    float c[4][4][4];
#pragma unroll
    for (int mi = 0; mi < 4; mi++)
#pragma unroll
        for (int ni = 0; ni < 4; ni++)
#pragma unroll
            for (int r = 0; r < 4; r++) c[mi][ni][r] = 0.0f;

    if (tid == 0) {
#pragma unroll
        for (int s = 0; s < NSTAGE; s++) {
            if (s < nkc_run) {
                uint32_t sb = sdata + s * STAGE_BYTES;
                expect_tx(mb + s * 8, 16384u);
                bulk_g2s(sb,        Asrc + (size_t)s * 4096, 8192, mb + s * 8);
                bulk_g2s(sb + 8192, Bsrc + (size_t)s * 4096, 8192, mb + s * 8);
            }
        }
    }

    const int rA_l = lane & 15;
    const int ckA_l = lane >> 4;
    const int rB_l = (lane & 7) + ((lane >> 4) << 3);
    const int ckB_l = (lane >> 3) & 1;

    for (int i = 0; i < nkc_run; i++) {
        const int s = i & (NSTAGE - 1);
        const int ph = (i >> 2) & 1;
        mbar_wait(mb + s * 8, ph);

        const uint32_t sA = sdata + s * STAGE_BYTES;
        const uint32_t sB = sA + 8192;

#pragma unroll
        for (int ks = 0; ks < 2; ks++) {
            uint32_t a[4][4];
#pragma unroll
            for (int mi = 0; mi < 4; mi++) {
                int r = wm * 64 + mi * 16 + rA_l;
                int ck = ks * 2 + ckA_l;
                ldmx4(a[mi], sA + r * 64 + ((ck ^ ((r >> 1) & 3)) << 4));
            }
            uint32_t b[4][2];
            {
                int ck = ks * 2 + ckB_l;
#pragma unroll
                for (int p = 0; p < 2; p++) {
                    int r = wn * 32 + p * 16 + rB_l;
                    uint32_t d[4];
                    ldmx4(d, sB + r * 64 + ((ck ^ ((r >> 1) & 3)) << 4));
                    b[p * 2][0] = d[0]; b[p * 2][1] = d[1];
                    b[p * 2 + 1][0] = d[2]; b[p * 2 + 1][1] = d[3];
                }
            }
#pragma unroll
            for (int mi = 0; mi < 4; mi++)
#pragma unroll
                for (int ni = 0; ni < 4; ni++) mma16816(c[mi][ni], a[mi], b[ni]);
        }
        if ((i & 1) && i + 3 < nkc_run + 2) {
            __syncthreads();
            if (tid == 0) {
#pragma unroll
                for (int q = 3; q <= 4; q++) {
                    int j = i + q;
                    if (j < nkc_run) {
                        const int s2 = j & (NSTAGE - 1);
                        uint32_t sb = sdata + s2 * STAGE_BYTES;
                        expect_tx(mb + s2 * 8, 16384u);
                        bulk_g2s(sb,        Asrc + (size_t)j * 4096, 8192, mb + s2 * 8);
                        bulk_g2s(sb + 8192, Bsrc + (size_t)j * 4096, 8192, mb + s2 * 8);
                    }
                }
            }
        }
    }

#pragma unroll
    for (int mi = 0; mi < 4; mi++) {
        int row = mt * 128 + wm * 64 + mi * 16 + (lane >> 2);
#pragma unroll
        for (int ni = 0; ni < 4; ni++) {
            int col = nt * 128 + wn * 32 + ni * 8 + (lane & 3) * 2;
            if (col < Nreal) {
                float2 v0 = {c[mi][ni][0], c[mi][ni][1]};
                float2 v1 = {c[mi][ni][2], c[mi][ni][3]};
                *(float2*)(C + (size_t)row * ldc + col) = v0;
                *(float2*)(C + (size_t)(row + 8) * ldc + col) = v1;
            }
        }
    }
}

// ---------------------------------------------------------------------------
// Attention v2: 4 queries x 1 kv-head per block, 160 threads.
// QK as before (K rows in registers). p repacked as float4 over queries;
// PV splits the d-dimension across 4 warps so V is read from shared ONCE
// per head (not 4x). Lane parity covers j/j+1. Vectorized packed stores.
// ---------------------------------------------------------------------------
#define KV_PITCH 66
#define VS_FLOATS 8648    // 131*66 = 8646, padded: keeps qsm 16B-aligned
#define SC4_FLOATS 656    // 164 j-slots * float4
#define ATTN_SMEM ((VS_FLOATS + 2048 + SC4_FLOATS + 32 + 32 + 4 + 256 + 12) * 4)

__global__ __launch_bounds__(160, 3) void attn_kernel(
    const float* __restrict__ qkv, const float* __restrict__ sinks,
    __half* __restrict__ cpk)
{
    extern __shared__ float sm[];
    float* vs    = sm;                          // VS_FLOATS
    float* qsm   = vs + VS_FLOATS;              // 2048 (16B-aligned)
    float* sc4   = qsm + 2048;                  // 656  (16B-aligned)
    float* redm  = sc4 + SC4_FLOATS;            // 32
    float* reds  = redm + 32;                   // 32
    float* denms = reds + 32;                   // 4
    float* ctxs  = denms + 4;                   // 256

    const int q0  = blockIdx.x * 4;
    const int kh  = blockIdx.y;
    const int b   = blockIdx.z;
    const int tid = threadIdx.x;
    const int lane = tid & 31, w = tid >> 5;
    const int kstartU = (q0 >= 127) ? q0 - 127 : 0;
    const int cntU = q0 + 3 - kstartU + 1;

    for (int i = tid; i < 2048; i += 160) {
        int qq = i >> 9, r = i & 511;
        qsm[r * 4 + qq] = qkv[(size_t)(b * S_LEN + q0 + qq) * QKV_COLS + kh * 512 + r];
    }
    for (int i = tid; i < cntU * 64; i += 160) {
        int r = i >> 6, d = i & 63;
        size_t rb = (size_t)(b * S_LEN + kstartU + r) * QKV_COLS;
        vs[r * KV_PITCH + d] = qkv[rb + 4608 + kh * 64 + d];
    }

    const bool havek = tid < cntU;
    float kreg[64];
    if (havek) {
        const float4* kp = (const float4*)(qkv +
            (size_t)(b * S_LEN + kstartU + tid) * QKV_COLS + 4096 + kh * 64);
#pragma unroll
        for (int u = 0; u < 16; u++) {
            float4 v = kp[u];
            kreg[u * 4 + 0] = v.x; kreg[u * 4 + 1] = v.y;
            kreg[u * 4 + 2] = v.z; kreg[u * 4 + 3] = v.w;
        }
    } else {
#pragma unroll
        for (int d = 0; d < 64; d++) kreg[d] = 0.0f;
    }
    __syncthreads();

    const int kpos = kstartU + tid;
    const int jj = lane >> 4;           // PV: j parity
    const int dd = (w << 4) + (lane & 15);   // PV: dim owned by this lane (w<4)

    for (int h8 = 0; h8 < 8; h8++) {
        const float sink = sinks[kh * 8 + h8];
        float s[4] = {-1e30f, -1e30f, -1e30f, -1e30f};
        if (havek) {
            float a0 = 0.f, a1 = 0.f, a2 = 0.f, a3 = 0.f;
            const float4* qp = (const float4*)(qsm + h8 * 256);
#pragma unroll
            for (int d = 0; d < 64; d++) {
                float4 qv = qp[d];
                float kd = kreg[d];
                a0 = fmaf(kd, qv.x, a0);
                a1 = fmaf(kd, qv.y, a1);
                a2 = fmaf(kd, qv.z, a2);
                a3 = fmaf(kd, qv.w, a3);
            }
            float aa[4] = {a0, a1, a2, a3};
#pragma unroll
            for (int qq = 0; qq < 4; qq++) {
                int qg = q0 + qq;
                int loG = qg - 127; if (loG < 0) loG = 0;
                s[qq] = (kpos >= loG && kpos <= qg) ? aa[qq] * 0.125f : -1e30f;
            }
        }
#pragma unroll
        for (int qq = 0; qq < 4; qq++) {
            float m = s[qq];
#pragma unroll
            for (int o = 16; o; o >>= 1) m = fmaxf(m, __shfl_xor_sync(0xffffffffu, m, o));
            if (lane == 0) redm[qq * 8 + w] = m;
        }
        __syncthreads();
        float mq[4];
#pragma unroll
        for (int qq = 0; qq < 4; qq++) {
            float m = redm[qq * 8];
#pragma unroll
            for (int j = 1; j < 5; j++) m = fmaxf(m, redm[qq * 8 + j]);
            mq[qq] = fmaxf(m, sink);
        }
        // p for all 4 queries: one STS.128 per thread + warp sums
        float4 p4;
        p4.x = fexp(s[0] - mq[0]);
        p4.y = fexp(s[1] - mq[1]);
        p4.z = fexp(s[2] - mq[2]);
        p4.w = fexp(s[3] - mq[3]);
        *(float4*)(sc4 + tid * 4) = p4;
        {
            float pr[4] = {p4.x, p4.y, p4.z, p4.w};
#pragma unroll
            for (int qq = 0; qq < 4; qq++) {
                float p = pr[qq];
#pragma unroll
                for (int o = 16; o; o >>= 1) p += __shfl_xor_sync(0xffffffffu, p, o);
                if (lane == 0) reds[qq * 8 + w] = p;
            }
        }
        __syncthreads();
        if (tid < 4) {
            float sum = reds[tid * 8] + reds[tid * 8 + 1] + reds[tid * 8 + 2] +
                        reds[tid * 8 + 3] + reds[tid * 8 + 4];
            denms[tid] = sum + fexp(sink - mq[tid]);
        }

        // PV: warp w owns dims [16w,16w+16); lanes split j parity; V read once.
        if (w < 4) {
            float a0 = 0.f, a1 = 0.f, a2 = 0.f, a3 = 0.f;
            for (int j0 = 0; j0 < cntU; j0 += 2) {
                int j = j0 + jj;
                if (j < cntU) {
                    float4 pv = *(const float4*)(sc4 + j * 4);
                    float v = vs[j * KV_PITCH + dd];
                    a0 = fmaf(pv.x, v, a0);
                    a1 = fmaf(pv.y, v, a1);
                    a2 = fmaf(pv.z, v, a2);
                    a3 = fmaf(pv.w, v, a3);
                }
            }
            a0 += __shfl_xor_sync(0xffffffffu, a0, 16);
            a1 += __shfl_xor_sync(0xffffffffu, a1, 16);
            a2 += __shfl_xor_sync(0xffffffffu, a2, 16);
            a3 += __shfl_xor_sync(0xffffffffu, a3, 16);
            if (lane < 16) {
                ctxs[0 * 64 + dd] = a0;
                ctxs[1 * 64 + dd] = a1;
                ctxs[2 * 64 + dd] = a2;
                ctxs[3 * 64 + dd] = a3;
            }
        }
        __syncthreads();

        // write phase: one warp emits vectorized packed stores
        if (tid < 32) {
            int qq = tid >> 3, ck = tid & 7;
            float inv = 1.0f / denms[qq];
            const float* src = ctxs + qq * 64 + ck * 8;
            __half h[8];
#pragma unroll
            for (int u = 0; u < 8; u++)
                h[u] = __float2half_rn(src[u] * inv);
            int t = b * S_LEN + q0 + qq;
            int kcol = (kh * 8 + h8) * 64 + ck * 8;
            *(uint4*)(cpk + offP(t, kcol, NKC_O)) = *(const uint4*)h;
        }
        __syncthreads();
    }
}

// ---------------------------------------------------------------------------
// Launch
// ---------------------------------------------------------------------------
extern "C" void kernel_launch(void* const* d_in, const int* in_sizes, int n_in,
                              void* d_out, int out_size) {
    const float* x     = (const float*)d_in[0];
    const float* wq    = (const float*)d_in[1];
    const float* bq    = (const float*)d_in[2];
    const float* wk    = (const float*)d_in[3];
    const float* bk    = (const float*)d_in[4];
    const float* wv    = (const float*)d_in[5];
    const float* bv    = (const float*)d_in[6];
    const float* wo    = (const float*)d_in[7];
    const float* bo    = (const float*)d_in[8];
    const float* sinks = (const float*)d_in[9];
    const int* positions = (const int*)d_in[10];
    float* out = (float*)d_out;

    void *xpk, *wbh, *wobh, *cpk, *qkv, *qkvp_part, *opart, *biasqkv;
    cudaGetSymbolAddress(&xpk, g_xpk);
    cudaGetSymbolAddress(&wbh, g_wbh);
    cudaGetSymbolAddress(&wobh, g_wobh);
    cudaGetSymbolAddress(&cpk, g_cpk);
    cudaGetSymbolAddress(&qkv, g_qkv);
    cudaGetSymbolAddress(&qkvp_part, g_qkvp);
    cudaGetSymbolAddress(&opart, g_opart);
    cudaGetSymbolAddress(&biasqkv, g_biasqkv);

    float* qkvp = (float*)qkv;
    float* qkvpartp = (float*)qkvp_part;
    float* opartp = (float*)opart;

    cudaFuncSetAttribute(gemm_tc, cudaFuncAttributeMaxDynamicSharedMemorySize, GEMM_SMEM);
    cudaFuncSetAttribute(attn_kernel, cudaFuncAttributeMaxDynamicSharedMemorySize, ATTN_SMEM);

    // 1. all prep in one launch
    prep_all<<<PREP_TOTAL, 256>>>(x, wq, wk, wv, wo, bq, bk, bv,
                                  (__half*)xpk, (__half*)wbh, (__half*)wobh,
                                  (float*)biasqkv);

    // 2. QKV projection: split-K=2 in one launch (z), then fused combine+rope
    gemm_tc<<<dim3(QKV_COLS / 128, T_TOK / 128, 2), 256, GEMM_SMEM>>>(
        (const __half*)xpk, (const __half*)wbh, qkvpartp,
        NKC_QKV, NKC_QKV / 2, QKV_COLS, QKV_COLS, (size_t)T_TOK * QKV_COLS);
    combine_qkv_rope<<<T_TOK, 256>>>(qkvpartp, (const float*)biasqkv, positions, qkvp);

    // 3. attention (writes packed fp16 ctx)
    attn_kernel<<<dim3(S_LEN / 4, 8, B_BATCH), 160, ATTN_SMEM>>>(
        qkvp, sinks, (__half*)cpk);

    // 4. output projection: split-K=2 in one launch (z), then combine (+bias)
    gemm_tc<<<dim3(OPAD / 128, T_TOK / 128, 2), 256, GEMM_SMEM>>>(
        (const __half*)cpk, (const __half*)wobh, opartp,
        NKC_O, NKC_O / 2, OPAD, OPAD, (size_t)T_TOK * OPAD);
    combine_o<<<T_TOK, 256>>>(opartp, bo, out);
}

// round 16
// speedup vs baseline: 1.9174x; 1.6539x over previous
#include <cuda_runtime.h>
#include <cuda_fp16.h>
#include <cstdint>

// ---------------------------------------------------------------------------
// Problem constants
// ---------------------------------------------------------------------------
#define T_TOK   2048
#define D_DIM   2880
#define S_LEN   1024
#define B_BATCH 2
#define WIN     128
#define NH      4096
#define KVH     512
#define QKV_COLS 5120
#define OPAD    2944
#define NKC_QKV 90        // 2880/32
#define NKC_O   128       // 4096/32

// ---------------------------------------------------------------------------
// Scratch
// ---------------------------------------------------------------------------
__device__ __half g_xpk [(size_t)16 * NKC_QKV * 128 * 32];   // x packed fp16 (A blobs)
__device__ __half g_wbh [(size_t)40 * NKC_QKV * 128 * 32];   // qkv weights (B blobs)
__device__ __half g_wobh[(size_t)23 * NKC_O   * 128 * 32];   // wo (B blobs)
__device__ __half g_cpk [(size_t)16 * NKC_O   * 128 * 32];   // ctx packed fp16 (A blobs)
__device__ float  g_qkv  [(size_t)T_TOK * QKV_COLS];
__device__ float  g_qkvp [(size_t)2 * T_TOK * QKV_COLS];     // QKV split-K partials
__device__ float  g_opart[(size_t)2 * T_TOK * OPAD];         // O split-K partials
__device__ float  g_biasqkv[QKV_COLS];

// ---------------------------------------------------------------------------
// Packed layout: 128-row x 32-k tiles, row = 64B, 16B chunks XOR-swizzled by
// ((row>>1)&3) so ldmatrix is conflict-free while bulk copies stay linear.
// ---------------------------------------------------------------------------
__device__ __forceinline__ size_t offP(int r_glob, int k, int nkc) {
    int r = r_glob & 127, ck = (k >> 3) & 3, w = k & 7;
    return ((((size_t)(r_glob >> 7)) * nkc + (k >> 5)) * 128 + r) * 32 +
           (((ck ^ ((r >> 1) & 3)) << 3) + w);
}

// ---------------------------------------------------------------------------
// PTX helpers
// ---------------------------------------------------------------------------
__device__ __forceinline__ void mbar_init(uint32_t a, uint32_t cnt) {
    asm volatile("mbarrier.init.shared.b64 [%0], %1;" :: "r"(a), "r"(cnt) : "memory");
}
__device__ __forceinline__ void mbar_wait(uint32_t a, int ph) {
    uint32_t done = 0;
    while (!done) {
        asm volatile("{\n\t.reg .pred p;\n\t"
                     "mbarrier.try_wait.parity.acquire.cta.shared::cta.b64 p, [%1], %2, 0x989680;\n\t"
                     "selp.b32 %0,1,0,p;\n\t}"
                     : "=r"(done) : "r"(a), "r"((uint32_t)ph) : "memory");
    }
}
__device__ __forceinline__ void expect_tx(uint32_t a, uint32_t bytes) {
    asm volatile("mbarrier.arrive.expect_tx.shared::cta.b64 _, [%0], %1;"
                 :: "r"(a), "r"(bytes) : "memory");
}
__device__ __forceinline__ void bulk_g2s(uint32_t sdst, const void* gsrc,
                                         uint32_t bytes, uint32_t mbar) {
    asm volatile("cp.async.bulk.shared::cluster.global.mbarrier::complete_tx::bytes "
                 "[%0], [%1], %2, [%3];"
                 :: "r"(sdst), "l"(__cvta_generic_to_global(gsrc)), "r"(bytes), "r"(mbar)
                 : "memory");
}
__device__ __forceinline__ void ldmx4(uint32_t* d, uint32_t addr) {
    asm volatile("ldmatrix.sync.aligned.m8n8.x4.shared.b16 {%0,%1,%2,%3}, [%4];"
                 : "=r"(d[0]), "=r"(d[1]), "=r"(d[2]), "=r"(d[3]) : "r"(addr));
}
__device__ __forceinline__ void mma16816(float* c, const uint32_t* a, const uint32_t* b) {
    asm volatile(
        "mma.sync.aligned.m16n8k16.row.col.f32.f16.f16.f32 "
        "{%0,%1,%2,%3},{%4,%5,%6,%7},{%8,%9},{%0,%1,%2,%3};\n"
        : "+f"(c[0]), "+f"(c[1]), "+f"(c[2]), "+f"(c[3])
        : "r"(a[0]), "r"(a[1]), "r"(a[2]), "r"(a[3]), "r"(b[0]), "r"(b[1]));
}

// fast exp on the FMA pipe (x <= 0 path), rel err ~1e-7
__device__ __forceinline__ float fexp(float x) {
    x = fmaxf(x, -87.0f);
    float y = x * 1.44269504f;
    float n = rintf(y);
    float f = y - n;
    float p = 1.33336498e-3f;
    p = fmaf(p, f, 9.61011233e-3f);
    p = fmaf(p, f, 5.55040755e-2f);
    p = fmaf(p, f, 2.40226507e-1f);
    p = fmaf(p, f, 6.93147182e-1f);
    p = fmaf(p, f, 1.0f);
    return p * __int_as_float(((int)n + 127) << 23);
}

// ---------------------------------------------------------------------------
// Fused prep (unchanged)
// ---------------------------------------------------------------------------
__device__ void dev_tsp(const float* __restrict__ in, __half* __restrict__ oh,
                        float (*tb)[65], int C, int nkc, int nbase,
                        int bx, int by, int tid) {
    int c0 = bx * 64, r0 = by * 64;
    int tx = tid & 31, ty = tid >> 5;
#pragma unroll
    for (int i = 0; i < 8; i++) {
        int r = r0 + ty + i * 8;
#pragma unroll
        for (int cc = 0; cc < 2; cc++) {
            int c = c0 + cc * 32 + tx;
            tb[ty + i * 8][cc * 32 + tx] = (c < C) ? in[(size_t)r * C + c] : 0.0f;
        }
    }
    __syncthreads();
    int nrow = tid >> 2;
    int ckg = tid & 3;
    int n = nbase + c0 + nrow;
#pragma unroll
    for (int half = 0; half < 2; half++) {
        int ck = ckg + half * 4;
        int k = r0 + ck * 8;
        __half h[8];
#pragma unroll
        for (int w = 0; w < 8; w++)
            h[w] = __float2half_rn(tb[ck * 8 + w][nrow]);
        *(uint4*)(oh + offP(n, k, nkc)) = *(const uint4*)h;
    }
}

__device__ void dev_pack_x(const float* __restrict__ x, __half* __restrict__ o,
                           int blk, int tid) {
    int gw = blk * 8 + (tid >> 5);
    int lane = tid & 31;
    int kt = gw % NKC_QKV;
    int tb = gw / NKC_QKV;
    if (tb >= T_TOK / 8) return;
    int j = lane >> 2, c = lane & 3;
    int t = tb * 8 + j;
    int k = kt * 32 + c * 8;
    const float* src = x + (size_t)t * D_DIM + k;
    float4 v0 = *(const float4*)src;
    float4 v1 = *(const float4*)(src + 4);
    __half h[8];
    h[0] = __float2half_rn(v0.x); h[1] = __float2half_rn(v0.y);
    h[2] = __float2half_rn(v0.z); h[3] = __float2half_rn(v0.w);
    h[4] = __float2half_rn(v1.x); h[5] = __float2half_rn(v1.y);
    h[6] = __float2half_rn(v1.z); h[7] = __float2half_rn(v1.w);
    *(uint4*)(o + offP(t, k, NKC_QKV)) = *(const uint4*)h;
}

#define PREP_WQ_END   2880
#define PREP_WK_END   3240
#define PREP_WV_END   3600
#define PREP_WO_END   6544
#define PREP_X_END    9424
#define PREP_TOTAL    9444

__global__ __launch_bounds__(256) void prep_all(
    const float* __restrict__ x,  const float* __restrict__ wq,
    const float* __restrict__ wk, const float* __restrict__ wv,
    const float* __restrict__ wo, const float* __restrict__ bq,
    const float* __restrict__ bk, const float* __restrict__ bv,
    __half* __restrict__ xpk, __half* __restrict__ wbh,
    __half* __restrict__ wobh, float* __restrict__ biasqkv)
{
    __shared__ float tb[64][65];
    int blk = blockIdx.x;
    int tid = threadIdx.x;
    if (blk < PREP_WQ_END) {
        dev_tsp(wq, wbh, tb, NH, NKC_QKV, 0, blk % 64, blk / 64, tid);
    } else if (blk < PREP_WK_END) {
        blk -= PREP_WQ_END;
        dev_tsp(wk, wbh, tb, KVH, NKC_QKV, NH, blk % 8, blk / 8, tid);
    } else if (blk < PREP_WV_END) {
        blk -= PREP_WK_END;
        dev_tsp(wv, wbh, tb, KVH, NKC_QKV, NH + KVH, blk % 8, blk / 8, tid);
    } else if (blk < PREP_WO_END) {
        blk -= PREP_WV_END;
        dev_tsp(wo, wobh, tb, D_DIM, NKC_O, 0, blk % 46, blk / 46, tid);
    } else if (blk < PREP_X_END) {
        dev_pack_x(x, xpk, blk - PREP_WO_END, tid);
    } else {
        int i = (blk - PREP_X_END) * 256 + tid;
        if (i < QKV_COLS)
            biasqkv[i] = (i < NH) ? bq[i] : (i < NH + KVH ? bk[i - NH] : bv[i - NH - KVH]);
    }
}

// ---------------------------------------------------------------------------
// Fused: combine QKV split-K partials + bias + RoPE (unchanged)
// ---------------------------------------------------------------------------
__global__ __launch_bounds__(256) void combine_qkv_rope(
    const float* __restrict__ part, const float* __restrict__ bias,
    const int* __restrict__ positions, float* __restrict__ qkv)
{
    __shared__ float row[NH + KVH];
    __shared__ float cs[32], sn[32];
    const int t = blockIdx.x;
    const int tid = threadIdx.x;

    if (tid < 32) {
        int i = tid;
        int pos = positions[t] % S_LEN;
        float freq   = powf(150000.0f, (float)i / 32.0f);
        float interp = 1.0f / (32.0f * freq);
        float extrap = 1.0f / freq;
        float lnT    = logf(150000.0f);
        float low    = 32.0f * logf(4096.0f / (32.0f * 6.2831853071795864f)) / lnT;
        float high   = 32.0f * logf(4096.0f / 6.2831853071795864f) / lnT;
        float ramp   = fminf(fmaxf(((float)i - low) / (high - low), 0.0f), 1.0f);
        float inv    = interp * ramp + extrap * (1.0f - ramp);
        float conc   = 0.1f * logf(32.0f) + 1.0f;
        float tt     = (float)pos * inv;
        cs[i] = cosf(tt) * conc;
        sn[i] = sinf(tt) * conc;
    }

    const float* p0 = part + (size_t)t * QKV_COLS;
    const float* p1 = part + (size_t)T_TOK * QKV_COLS + (size_t)t * QKV_COLS;
    float* orow = qkv + (size_t)t * QKV_COLS;

    for (int c = tid * 4; c < QKV_COLS; c += 256 * 4) {
        float4 a = *(const float4*)(p0 + c);
        float4 b = *(const float4*)(p1 + c);
        float4 bb = *(const float4*)(bias + c);
        float4 r;
        r.x = a.x + b.x + bb.x;
        r.y = a.y + b.y + bb.y;
        r.z = a.z + b.z + bb.z;
        r.w = a.w + b.w + bb.w;
        if (c >= NH + KVH) {
            *(float4*)(orow + c) = r;
        } else {
            *(float4*)(row + c) = r;
        }
    }
    __syncthreads();

    for (int idx = tid; idx < 72 * 32; idx += 256) {
        int head = idx >> 5, i = idx & 31;
        float x1 = row[head * 64 + i], x2 = row[head * 64 + i + 32];
        orow[head * 64 + i]      = x1 * cs[i] - x2 * sn[i];
        orow[head * 64 + i + 32] = x2 * cs[i] + x1 * sn[i];
    }
}

// combine O split-K partials + bias -> final output [T, 2880]
__global__ void combine_o(const float* __restrict__ part, const float* __restrict__ bo,
                          float* __restrict__ out) {
    const int t = blockIdx.x;
    const float* p0 = part + (size_t)t * OPAD;
    const float* p1 = part + (size_t)T_TOK * OPAD + (size_t)t * OPAD;
    float* o = out + (size_t)t * D_DIM;
    for (int c = threadIdx.x * 4; c < D_DIM; c += 256 * 4) {
        float4 a = *(const float4*)(p0 + c);
        float4 b = *(const float4*)(p1 + c);
        float4 bb = *(const float4*)(bo + c);
        float4 r;
        r.x = a.x + b.x + bb.x;
        r.y = a.y + b.y + bb.y;
        r.z = a.z + b.z + bb.z;
        r.w = a.w + b.w + bb.w;
        *(float4*)(o + c) = r;
    }
}

// ---------------------------------------------------------------------------
// GEMM (unchanged)
// ---------------------------------------------------------------------------
#define STAGE_BYTES 16384
#define NSTAGE      4
#define GEMM_SMEM   (128 + NSTAGE * STAGE_BYTES)

__global__ __launch_bounds__(256, 2) void gemm_tc(
    const __half* __restrict__ Apk, const __half* __restrict__ Bhp,
    float* __restrict__ C,
    int nkc_total, int nkc_run, int Nreal, int ldc, size_t plane_stride)
{
    extern __shared__ __align__(128) uint8_t dsm[];
    const uint32_t base = (uint32_t)__cvta_generic_to_shared(dsm);
    const uint32_t mb = base;
    const uint32_t sdata = base + 128;

    const int tid = threadIdx.x, lane = tid & 31, warp = tid >> 5;
    const int wm = warp >> 2, wn = warp & 3;
    const int mt = blockIdx.y, nt = blockIdx.x;
    const int kbase = blockIdx.z * nkc_run;
    C += (size_t)blockIdx.z * plane_stride;

    if (tid == 0)
#pragma unroll
        for (int s = 0; s < NSTAGE; s++) mbar_init(mb + s * 8, 1);
    __syncthreads();

    const __half* Asrc = Apk + (size_t)mt * nkc_total * 4096 + (size_t)kbase * 4096;
    const __half* Bsrc = Bhp + (size_t)nt * nkc_total * 4096 + (size_t)kbase * 4096;

    float c[4][4][4];
#pragma unroll
    for (int mi = 0; mi < 4; mi++)
#pragma unroll
        for (int ni = 0; ni < 4; ni++)
#pragma unroll
            for (int r = 0; r < 4; r++) c[mi][ni][r] = 0.0f;

    if (tid == 0) {
#pragma unroll
        for (int s = 0; s < NSTAGE; s++) {
            if (s < nkc_run) {
                uint32_t sb = sdata + s * STAGE_BYTES;
                expect_tx(mb + s * 8, 16384u);
                bulk_g2s(sb,        Asrc + (size_t)s * 4096, 8192, mb + s * 8);
                bulk_g2s(sb + 8192, Bsrc + (size_t)s * 4096, 8192, mb + s * 8);
            }
        }
    }

    const int rA_l = lane & 15;
    const int ckA_l = lane >> 4;
    const int rB_l = (lane & 7) + ((lane >> 4) << 3);
    const int ckB_l = (lane >> 3) & 1;

    for (int i = 0; i < nkc_run; i++) {
        const int s = i & (NSTAGE - 1);
        const int ph = (i >> 2) & 1;
        mbar_wait(mb + s * 8, ph);

        const uint32_t sA = sdata + s * STAGE_BYTES;
        const uint32_t sB = sA + 8192;

#pragma unroll
        for (int ks = 0; ks < 2; ks++) {
            uint32_t a[4][4];
#pragma unroll
            for (int mi = 0; mi < 4; mi++) {
                int r = wm * 64 + mi * 16 + rA_l;
                int ck = ks * 2 + ckA_l;
                ldmx4(a[mi], sA + r * 64 + ((ck ^ ((r >> 1) & 3)) << 4));
            }
            uint32_t b[4][2];
            {
                int ck = ks * 2 + ckB_l;
#pragma unroll
                for (int p = 0; p < 2; p++) {
                    int r = wn * 32 + p * 16 + rB_l;
                    uint32_t d[4];
                    ldmx4(d, sB + r * 64 + ((ck ^ ((r >> 1) & 3)) << 4));
                    b[p * 2][0] = d[0]; b[p * 2][1] = d[1];
                    b[p * 2 + 1][0] = d[2]; b[p * 2 + 1][1] = d[3];
                }
            }
#pragma unroll
            for (int mi = 0; mi < 4; mi++)
#pragma unroll
                for (int ni = 0; ni < 4; ni++) mma16816(c[mi][ni], a[mi], b[ni]);
        }
        if ((i & 1) && i + 3 < nkc_run + 2) {
            __syncthreads();
            if (tid == 0) {
#pragma unroll
                for (int q = 3; q <= 4; q++) {
                    int j = i + q;
                    if (j < nkc_run) {
                        const int s2 = j & (NSTAGE - 1);
                        uint32_t sb = sdata + s2 * STAGE_BYTES;
                        expect_tx(mb + s2 * 8, 16384u);
                        bulk_g2s(sb,        Asrc + (size_t)j * 4096, 8192, mb + s2 * 8);
                        bulk_g2s(sb + 8192, Bsrc + (size_t)j * 4096, 8192, mb + s2 * 8);
                    }
                }
            }
        }
    }

#pragma unroll
    for (int mi = 0; mi < 4; mi++) {
        int row = mt * 128 + wm * 64 + mi * 16 + (lane >> 2);
#pragma unroll
        for (int ni = 0; ni < 4; ni++) {
            int col = nt * 128 + wn * 32 + ni * 8 + (lane & 3) * 2;
            if (col < Nreal) {
                float2 v0 = {c[mi][ni][0], c[mi][ni][1]};
                float2 v1 = {c[mi][ni][2], c[mi][ni][3]};
                *(float2*)(C + (size_t)row * ldc + col) = v0;
                *(float2*)(C + (size_t)(row + 8) * ldc + col) = v1;
            }
        }
    }
}

// ---------------------------------------------------------------------------
// Attention v3 — tensor-core. Block = (16 queries) x (8 GQA heads) of one
// kv-head: 128 score rows x 144 window cols. Warp w owns head w (16 rows),
// so softmax is warp-local (quad shfl). QK and PV on mma.m16n8k16; P rebuilt
// in registers from C fragments (C->A layout identity). V stored transposed.
// ---------------------------------------------------------------------------
#define QT 16                       // queries per block
#define NCOL 144                    // padded window
#define QPITCH 72                   // halves (144B; 9 x 16B -> ldmatrix conflict-free)
#define KPITCH 72
#define VPITCH 152                  // halves (304B; 19 x 16B -> conflict-free)
#define ATTN_SMEM (128 * QPITCH * 2 + NCOL * KPITCH * 2 + 64 * VPITCH * 2)

__global__ __launch_bounds__(256, 1) void attn_kernel(
    const float* __restrict__ qkv, const float* __restrict__ sinks,
    __half* __restrict__ cpk)
{
    extern __shared__ __align__(16) __half hsm[];
    __half* Qs = hsm;                        // [128][QPITCH]
    __half* Ks = Qs + 128 * QPITCH;          // [144][KPITCH]
    __half* Vt = Ks + NCOL * KPITCH;         // [64][VPITCH]  (dim-major)

    const uint32_t sQ = (uint32_t)__cvta_generic_to_shared(Qs);
    const uint32_t sK = (uint32_t)__cvta_generic_to_shared(Ks);
    const uint32_t sV = (uint32_t)__cvta_generic_to_shared(Vt);

    const int qt = blockIdx.x;
    const int kh = blockIdx.y;
    const int b  = blockIdx.z;
    const int tid = threadIdx.x;
    const int lane = tid & 31, w = tid >> 5;

    const int q0 = qt * QT;
    const int kstart = (q0 >= 127) ? q0 - 127 : 0;
    const int cnt = q0 + QT - 1 - kstart + 1;   // <= 143

    // ---- stage Q (fp16, row = head*16 + query) ----
    for (int i = tid; i < 128 * 64; i += 256) {
        int row = i >> 6, d = i & 63;
        int h8 = row >> 4, qq = row & 15;
        Qs[row * QPITCH + d] = __float2half_rn(
            qkv[(size_t)(b * S_LEN + q0 + qq) * QKV_COLS + kh * 512 + h8 * 64 + d]);
    }
    // ---- stage K rows and V transposed; zero tail ----
    for (int i = tid; i < NCOL * 64; i += 256) {
        int col = i >> 6, d = i & 63;
        float kv = 0.0f, vv = 0.0f;
        if (col < cnt) {
            size_t rb = (size_t)(b * S_LEN + kstart + col) * QKV_COLS;
            kv = qkv[rb + 4096 + kh * 64 + d];
            vv = qkv[rb + 4608 + kh * 64 + d];
        }
        Ks[col * KPITCH + d] = __float2half_rn(kv);
        Vt[d * VPITCH + col] = __float2half_rn(vv);
    }
    __syncthreads();

    // ---- QK^T: warp w computes scores for head w: 16 rows x 144 cols ----
    const int g = lane >> 2, tg = lane & 3;
    float c[18][4];
#pragma unroll
    for (int nt = 0; nt < 18; nt++)
#pragma unroll
        for (int r = 0; r < 4; r++) c[nt][r] = 0.0f;

    const uint32_t qaddr = sQ + ((w * 16 + (lane & 15)) * QPITCH + (lane >> 4) * 8) * 2;
    const uint32_t kaddr = sK + ((((lane & 7) + ((lane >> 4) << 3)) * KPITCH) +
                                 ((lane >> 3) & 1) * 8) * 2;
#pragma unroll
    for (int ks = 0; ks < 4; ks++) {
        uint32_t a[4];
        ldmx4(a, qaddr + ks * 32);
#pragma unroll
        for (int p = 0; p < 9; p++) {
            uint32_t d[4];
            ldmx4(d, kaddr + p * (16 * KPITCH * 2) + ks * 32);
            mma16816(c[p * 2],     a, d);
            mma16816(c[p * 2 + 1], a, d + 2);
        }
    }

    // ---- mask + scale + softmax (warp-local; rows g and g+8) ----
    const float sink = sinks[kh * 8 + w];
    const int qg0 = q0 + g, qg1 = q0 + g + 8;
#pragma unroll
    for (int nt = 0; nt < 18; nt++) {
#pragma unroll
        for (int r = 0; r < 4; r++) {
            int ci = nt * 8 + tg * 2 + (r & 1);
            int kpos = kstart + ci;
            int qg = (r < 2) ? qg0 : qg1;
            bool pred = (kpos <= qg) && (qg - kpos < WIN);
            c[nt][r] = pred ? c[nt][r] * 0.125f : -1e30f;
        }
    }
    float m0 = -1e30f, m1 = -1e30f;
#pragma unroll
    for (int nt = 0; nt < 18; nt++) {
        m0 = fmaxf(m0, fmaxf(c[nt][0], c[nt][1]));
        m1 = fmaxf(m1, fmaxf(c[nt][2], c[nt][3]));
    }
    m0 = fmaxf(m0, __shfl_xor_sync(0xffffffffu, m0, 1));
    m0 = fmaxf(m0, __shfl_xor_sync(0xffffffffu, m0, 2));
    m1 = fmaxf(m1, __shfl_xor_sync(0xffffffffu, m1, 1));
    m1 = fmaxf(m1, __shfl_xor_sync(0xffffffffu, m1, 2));
    m0 = fmaxf(m0, sink);
    m1 = fmaxf(m1, sink);

    float s0 = 0.0f, s1 = 0.0f;
#pragma unroll
    for (int nt = 0; nt < 18; nt++) {
        c[nt][0] = fexp(c[nt][0] - m0);
        c[nt][1] = fexp(c[nt][1] - m0);
        c[nt][2] = fexp(c[nt][2] - m1);
        c[nt][3] = fexp(c[nt][3] - m1);
        s0 += c[nt][0] + c[nt][1];
        s1 += c[nt][2] + c[nt][3];
    }
    s0 += __shfl_xor_sync(0xffffffffu, s0, 1);
    s0 += __shfl_xor_sync(0xffffffffu, s0, 2);
    s1 += __shfl_xor_sync(0xffffffffu, s1, 1);
    s1 += __shfl_xor_sync(0xffffffffu, s1, 2);
    const float inv0 = 1.0f / (s0 + fexp(sink - m0));
    const float inv1 = 1.0f / (s1 + fexp(sink - m1));

    // ---- PV: P (regs, fp16) x Vt -> o[8][4] ----
    float o[8][4];
#pragma unroll
    for (int nt = 0; nt < 8; nt++)
#pragma unroll
        for (int r = 0; r < 4; r++) o[nt][r] = 0.0f;

    const uint32_t vaddr = sV + ((((lane & 7) + ((lane >> 4) << 3)) * VPITCH) +
                                 ((lane >> 3) & 1) * 8) * 2;
#pragma unroll
    for (int kk = 0; kk < 9; kk++) {
        uint32_t a[4];
        __half2 h0 = __float22half2_rn(make_float2(c[2 * kk][0],     c[2 * kk][1]));
        __half2 h1 = __float22half2_rn(make_float2(c[2 * kk][2],     c[2 * kk][3]));
        __half2 h2 = __float22half2_rn(make_float2(c[2 * kk + 1][0], c[2 * kk + 1][1]));
        __half2 h3 = __float22half2_rn(make_float2(c[2 * kk + 1][2], c[2 * kk + 1][3]));
        a[0] = *(uint32_t*)&h0;
        a[1] = *(uint32_t*)&h1;
        a[2] = *(uint32_t*)&h2;
        a[3] = *(uint32_t*)&h3;
#pragma unroll
        for (int p = 0; p < 4; p++) {
            uint32_t d[4];
            ldmx4(d, vaddr + p * (16 * VPITCH * 2) + kk * 32);
            mma16816(o[p * 2],     a, d);
            mma16816(o[p * 2 + 1], a, d + 2);
        }
    }

    // ---- scale by 1/denom, store to packed cpk ----
    const int t0 = b * S_LEN + q0 + g;
    const int t1 = t0 + 8;
#pragma unroll
    for (int nt = 0; nt < 8; nt++) {
        int kcol = (kh * 8 + w) * 64 + nt * 8 + tg * 2;
        __half2 r0 = __float22half2_rn(make_float2(o[nt][0] * inv0, o[nt][1] * inv0));
        __half2 r1 = __float22half2_rn(make_float2(o[nt][2] * inv1, o[nt][3] * inv1));
        *(__half2*)(cpk + offP(t0, kcol, NKC_O)) = r0;
        *(__half2*)(cpk + offP(t1, kcol, NKC_O)) = r1;
    }
}

// ---------------------------------------------------------------------------
// Launch
// ---------------------------------------------------------------------------
extern "C" void kernel_launch(void* const* d_in, const int* in_sizes, int n_in,
                              void* d_out, int out_size) {
    const float* x     = (const float*)d_in[0];
    const float* wq    = (const float*)d_in[1];
    const float* bq    = (const float*)d_in[2];
    const float* wk    = (const float*)d_in[3];
    const float* bk    = (const float*)d_in[4];
    const float* wv    = (const float*)d_in[5];
    const float* bv    = (const float*)d_in[6];
    const float* wo    = (const float*)d_in[7];
    const float* bo    = (const float*)d_in[8];
    const float* sinks = (const float*)d_in[9];
    const int* positions = (const int*)d_in[10];
    float* out = (float*)d_out;

    void *xpk, *wbh, *wobh, *cpk, *qkv, *qkvp_part, *opart, *biasqkv;
    cudaGetSymbolAddress(&xpk, g_xpk);
    cudaGetSymbolAddress(&wbh, g_wbh);
    cudaGetSymbolAddress(&wobh, g_wobh);
    cudaGetSymbolAddress(&cpk, g_cpk);
    cudaGetSymbolAddress(&qkv, g_qkv);
    cudaGetSymbolAddress(&qkvp_part, g_qkvp);
    cudaGetSymbolAddress(&opart, g_opart);
    cudaGetSymbolAddress(&biasqkv, g_biasqkv);

    float* qkvp = (float*)qkv;
    float* qkvpartp = (float*)qkvp_part;
    float* opartp = (float*)opart;

    cudaFuncSetAttribute(gemm_tc, cudaFuncAttributeMaxDynamicSharedMemorySize, GEMM_SMEM);
    cudaFuncSetAttribute(attn_kernel, cudaFuncAttributeMaxDynamicSharedMemorySize, ATTN_SMEM);

    // 1. all prep in one launch
    prep_all<<<PREP_TOTAL, 256>>>(x, wq, wk, wv, wo, bq, bk, bv,
                                  (__half*)xpk, (__half*)wbh, (__half*)wobh,
                                  (float*)biasqkv);

    // 2. QKV projection: split-K=2 in one launch (z), then fused combine+rope
    gemm_tc<<<dim3(QKV_COLS / 128, T_TOK / 128, 2), 256, GEMM_SMEM>>>(
        (const __half*)xpk, (const __half*)wbh, qkvpartp,
        NKC_QKV, NKC_QKV / 2, QKV_COLS, QKV_COLS, (size_t)T_TOK * QKV_COLS);
    combine_qkv_rope<<<T_TOK, 256>>>(qkvpartp, (const float*)biasqkv, positions, qkvp);

    // 3. attention (tensor-core, writes packed fp16 ctx)
    attn_kernel<<<dim3(S_LEN / QT, 8, B_BATCH), 256, ATTN_SMEM>>>(
        qkvp, sinks, (__half*)cpk);

    // 4. output projection: split-K=2 in one launch (z), then combine (+bias)
    gemm_tc<<<dim3(OPAD / 128, T_TOK / 128, 2), 256, GEMM_SMEM>>>(
        (const __half*)cpk, (const __half*)wobh, opartp,
        NKC_O, NKC_O / 2, OPAD, OPAD, (size_t)T_TOK * OPAD);
    combine_o<<<T_TOK, 256>>>(opartp, bo, out);
}